// round 11
// baseline (speedup 1.0000x reference)
#include <cuda_runtime.h>
#include <cuda_bf16.h>
#include <stdint.h>
#include <math.h>

#define NB 8
#define NC 256
#define NP1 1024
#define NP2 256
#define NINNER 512
#define BN_EPS 1e-5f

// ---------------- bf16 hi/lo scratch ----------------
__device__ __nv_bfloat16 g_hq_h [2][NB][NC][NP1],      g_hq_l [2][NB][NC][NP1];
__device__ __nv_bfloat16 g_hkv_h[2][NB][NC][NP2],      g_hkv_l[2][NB][NC][NP2];
__device__ __nv_bfloat16 g_q_h  [2][NB][NINNER][NP1],  g_q_l  [2][NB][NINNER][NP1];
__device__ __nv_bfloat16 g_kv_h [2][NB][2*NINNER][NP2],g_kv_l [2][NB][2*NINNER][NP2];
__device__ __nv_bfloat16 g_ao_h [2][NB][NINNER][NP1],  g_ao_l [2][NB][NINNER][NP1];
__device__ __nv_bfloat16 g_wq_h [NINNER*NC],   g_wq_l [NINNER*NC];
__device__ __nv_bfloat16 g_wkv_h[2*NINNER*NC], g_wkv_l[2*NINNER*NC];
__device__ __nv_bfloat16 g_wo_h [NC*NINNER],   g_wo_l [NC*NINNER];

// ---------------- helpers ----------------
__device__ __forceinline__ uint32_t smem_u32(const void* p){
    uint32_t a;
    asm("{ .reg .u64 t; cvta.to.shared.u64 t, %1; cvt.u32.u64 %0, t; }" : "=r"(a) : "l"(p));
    return a;
}
__device__ __forceinline__ void ldmx4(uint32_t* r, uint32_t a){
    asm volatile("ldmatrix.sync.aligned.m8n8.x4.shared.b16 {%0,%1,%2,%3}, [%4];"
        : "=r"(r[0]),"=r"(r[1]),"=r"(r[2]),"=r"(r[3]) : "r"(a) : "memory");
}
__device__ __forceinline__ void ldmx4t(uint32_t* r, uint32_t a){
    asm volatile("ldmatrix.sync.aligned.m8n8.x4.trans.shared.b16 {%0,%1,%2,%3}, [%4];"
        : "=r"(r[0]),"=r"(r[1]),"=r"(r[2]),"=r"(r[3]) : "r"(a) : "memory");
}
__device__ __forceinline__ void mma16816(float* c, const uint32_t* a, const uint32_t* b){
    asm volatile("mma.sync.aligned.m16n8k16.row.col.f32.bf16.bf16.f32 "
        "{%0,%1,%2,%3}, {%4,%5,%6,%7}, {%8,%9}, {%0,%1,%2,%3};"
        : "+f"(c[0]),"+f"(c[1]),"+f"(c[2]),"+f"(c[3])
        : "r"(a[0]),"r"(a[1]),"r"(a[2]),"r"(a[3]),"r"(b[0]),"r"(b[1]));
}
__device__ __forceinline__ void cpa16(uint32_t s, const void* g){
    asm volatile("cp.async.cg.shared.global [%0], [%1], 16;" :: "r"(s), "l"(g));
}
#define CP_COMMIT() asm volatile("cp.async.commit_group;" ::: "memory")
#define CP_WAIT0()  asm volatile("cp.async.wait_group 0;" ::: "memory")
#define CP_WAIT1()  asm volatile("cp.async.wait_group 1;" ::: "memory")

__device__ __forceinline__ void put_hl(__nv_bfloat16* bh, __nv_bfloat16* bl, int idx, float v){
    __nv_bfloat16 h = __float2bfloat16(v);
    bh[idx] = h;
    bl[idx] = __float2bfloat16(v - __bfloat162float(h));
}
__device__ __forceinline__ void put_hl2(__nv_bfloat16* bh, __nv_bfloat16* bl, int idx, float v0, float v1){
    __nv_bfloat16 h0 = __float2bfloat16(v0), h1 = __float2bfloat16(v1);
    __nv_bfloat162 H; H.x = h0; H.y = h1;
    __nv_bfloat162 L;
    L.x = __float2bfloat16(v0 - __bfloat162float(h0));
    L.y = __float2bfloat16(v1 - __bfloat162float(h1));
    *(__nv_bfloat162*)(bh + idx) = H;
    *(__nv_bfloat162*)(bl + idx) = L;
}

// ---------------- weight fp32 -> hi/lo ----------------
__global__ void cvt_hl_kernel(const float* __restrict__ src, __nv_bfloat16* __restrict__ h,
                              __nv_bfloat16* __restrict__ l, int n2){
    int i = blockIdx.x * 256 + threadIdx.x;
    if (i < n2) {
        float2 v = *(const float2*)(src + i * 2);
        put_hl2(h, l, i * 2, v.x, v.y);
    }
}

// ---------------- fused depthwise conv (s1 + s2) + BN -> bf16 hi/lo ----------------
__global__ __launch_bounds__(256)
void dwbn_fused(const float* __restrict__ x0, const float* __restrict__ x1,
                const float* __restrict__ qw, const float* __restrict__ qg,
                const float* __restrict__ qb, const float* __restrict__ qm,
                const float* __restrict__ qv,
                const float* __restrict__ kw, const float* __restrict__ kg,
                const float* __restrict__ kb, const float* __restrict__ km,
                const float* __restrict__ kvv)
{
    int inp = blockIdx.y, bc = blockIdx.x, c = bc & 255, b = bc >> 8;
    const float* in = (inp ? x1 : x0) + (size_t)bc * 1024;
    __shared__ float t[34][36];
    int tid = threadIdx.x;

    if (tid < 34) { t[0][tid] = 0.f; t[33][tid] = 0.f; }
    else if (tid < 66) { int r = tid - 33; t[r][0] = 0.f; t[r][33] = 0.f; }

    {
        int r = tid >> 3, q = (tid & 7) * 4;
        float4 v = *(const float4*)(in + r * 32 + q);
        t[r + 1][q + 1] = v.x; t[r + 1][q + 2] = v.y;
        t[r + 1][q + 3] = v.z; t[r + 1][q + 4] = v.w;
    }

    float qwr[9], kwr[9];
#pragma unroll
    for (int i = 0; i < 9; i++) { qwr[i] = qw[c * 9 + i]; kwr[i] = kw[c * 9 + i]; }
    float qs  = qg[c] * rsqrtf(qv[c] + BN_EPS);
    float qsh = qb[c] - qm[c] * qs;
    float ks  = kg[c] * rsqrtf(kvv[c] + BN_EPS);
    float ksh = kb[c] - km[c] * ks;
    __syncthreads();

    {
        int oy = tid >> 3, ox = (tid & 7) * 4;
        float o0 = 0.f, o1 = 0.f, o2 = 0.f, o3 = 0.f;
#pragma unroll
        for (int dy = 0; dy < 3; dy++) {
            float a0 = t[oy + dy][ox + 0], a1 = t[oy + dy][ox + 1], a2 = t[oy + dy][ox + 2];
            float a3 = t[oy + dy][ox + 3], a4 = t[oy + dy][ox + 4], a5 = t[oy + dy][ox + 5];
            float w0 = qwr[dy * 3], w1 = qwr[dy * 3 + 1], w2 = qwr[dy * 3 + 2];
            o0 += a0 * w0 + a1 * w1 + a2 * w2;
            o1 += a1 * w0 + a2 * w1 + a3 * w2;
            o2 += a2 * w0 + a3 * w1 + a4 * w2;
            o3 += a3 * w0 + a4 * w1 + a5 * w2;
        }
        o0 = o0 * qs + qsh; o1 = o1 * qs + qsh;
        o2 = o2 * qs + qsh; o3 = o3 * qs + qsh;
        int idx = oy * 32 + ox;
        put_hl2(&g_hq_h[inp][b][c][0], &g_hq_l[inp][b][c][0], idx, o0, o1);
        put_hl2(&g_hq_h[inp][b][c][0], &g_hq_l[inp][b][c][0], idx + 2, o2, o3);
    }

    {
        int oy = tid >> 4, ox = tid & 15;
        float a = 0.f;
#pragma unroll
        for (int dy = 0; dy < 3; dy++)
#pragma unroll
            for (int dx = 0; dx < 3; dx++)
                a += t[oy * 2 + dy][ox * 2 + dx] * kwr[dy * 3 + dx];
        a = a * ks + ksh;
        put_hl(&g_hkv_h[inp][b][c][0], &g_hkv_l[inp][b][c][0], oy * 16 + ox, a);
    }
}

// ---------------- tensor-core GEMM v5: 3-stage pipeline, 1 sync/iter, 2 CTAs/SM ----------------
#define ALD2 40
#define BLD2 136
#define STG_SZ 37888            // per-stage: A_H 10240 | A_L 10240 | B_H 8704 | B_L 8704
#define OFF_AH 0
#define OFF_AL 10240
#define OFF_BH 20480
#define OFF_BL 29184
#define GSM3 (3 * STG_SZ)       // 113664
#define ELD 136                 // bf16 epilogue stage LD
#define ELDF 136                // fp32 epilogue stage LD (floats)

__global__ __launch_bounds__(256, 2)
void mm_gemm2(const __nv_bfloat16* __restrict__ Ah, const __nv_bfloat16* __restrict__ Al,
              const __nv_bfloat16* __restrict__ Bh, const __nv_bfloat16* __restrict__ Bl,
              __nv_bfloat16* __restrict__ Ch, __nv_bfloat16* __restrict__ Cl,
              float* __restrict__ Cf, const float* __restrict__ bias,
              int Mtot, int K, int P)
{
    extern __shared__ char sm[];
    uint32_t sb = smem_u32(sm);
    int tid = threadIdx.x, lane = tid & 31, wid = tid >> 5;
    int wr = wid >> 1, wc = wid & 1;
    int m0 = blockIdx.y * 128, n0 = blockIdx.x * 128;
    size_t zoff = (size_t)blockIdx.z * K * P;
    const __nv_bfloat16* Bhz = Bh + zoff;
    const __nv_bfloat16* Blz = Bl + zoff;

    float acc[2][8][4];
#pragma unroll
    for (int i = 0; i < 2; i++)
#pragma unroll
        for (int j = 0; j < 8; j++)
#pragma unroll
            for (int k = 0; k < 4; k++) acc[i][j][k] = 0.f;

    int niter = K >> 5;

#define LOAD_STAGE(base, k0) do { \
    _Pragma("unroll") \
    for (int u = 0; u < 2; u++) { \
        int idx = tid + u * 256; \
        int row = idx >> 2, ch = (idx & 3) * 8; \
        size_t go = (size_t)(m0 + row) * K + (k0) + ch; \
        uint32_t so = (uint32_t)(row * ALD2 + ch) * 2; \
        cpa16((base) + OFF_AH + so, Ah + go); \
        cpa16((base) + OFF_AL + so, Al + go); \
    } \
    _Pragma("unroll") \
    for (int u = 0; u < 2; u++) { \
        int idx = tid + u * 256; \
        int row = idx >> 4, ch = (idx & 15) * 8; \
        size_t go = (size_t)((k0) + row) * P + n0 + ch; \
        uint32_t so = (uint32_t)(row * BLD2 + ch) * 2; \
        cpa16((base) + OFF_BH + so, Bhz + go); \
        cpa16((base) + OFF_BL + so, Blz + go); \
    } \
} while (0)

    LOAD_STAGE(sb, 0);
    CP_COMMIT();
    LOAD_STAGE(sb + STG_SZ, 32);   // niter >= 2 always (K >= 64)
    CP_COMMIT();

    int st = 0;                    // stage index of current iter (mod 3)
    for (int it = 0; it < niter; it++) {
        if (it + 1 < niter) CP_WAIT1(); else CP_WAIT0();
        __syncthreads();

        // issue loads for it+2 (writes stage (it+2)%3 = (it-1)%3, fully read by all warps)
        if (it + 2 < niter) {
            int st2 = st + 2; if (st2 >= 3) st2 -= 3;
            LOAD_STAGE(sb + st2 * STG_SZ, (it + 2) << 5);
            CP_COMMIT();
        }

        uint32_t bse = sb + st * STG_SZ;
#pragma unroll
        for (int kk = 0; kk < 2; kk++) {
            uint32_t ah[2][4], al[2][4];
#pragma unroll
            for (int mi = 0; mi < 2; mi++) {
                uint32_t aaddr = bse + OFF_AH + (uint32_t)((wr*32 + mi*16 + (lane & 15)) * ALD2
                                                  + kk*16 + (lane >> 4) * 8) * 2;
                ldmx4(ah[mi], aaddr);
                ldmx4(al[mi], aaddr + (OFF_AL - OFF_AH));
            }
#pragma unroll
            for (int ni2 = 0; ni2 < 4; ni2++) {
                uint32_t bh[4], bl[4];
                uint32_t baddr = bse + OFF_BH + (uint32_t)((kk*16 + (lane & 15)) * BLD2
                                                  + wc*64 + ni2*16 + ((lane & 16) >> 1)) * 2;
                ldmx4t(bh, baddr);
                ldmx4t(bl, baddr + (OFF_BL - OFF_BH));
#pragma unroll
                for (int mi = 0; mi < 2; mi++) {
                    mma16816(acc[mi][ni2*2],   ah[mi], &bh[0]);
                    mma16816(acc[mi][ni2*2],   ah[mi], &bl[0]);
                    mma16816(acc[mi][ni2*2],   al[mi], &bh[0]);
                    mma16816(acc[mi][ni2*2+1], ah[mi], &bh[2]);
                    mma16816(acc[mi][ni2*2+1], ah[mi], &bl[2]);
                    mma16816(acc[mi][ni2*2+1], al[mi], &bh[2]);
                }
            }
        }
        if (++st == 3) st = 0;
    }
    __syncthreads();   // all warps done with smem before epilogue staging reuses it

    if (Cf) {
        // staged fp32 epilogue: fragments(+bias) -> smem, then coalesced float4 stores
        float* Ef = (float*)sm;   // 128 x ELDF floats = 69632 B
        float* Cp = Cf + (size_t)blockIdx.z * Mtot * P;
#pragma unroll
        for (int mi = 0; mi < 2; mi++) {
            int row = wr*32 + mi*16 + (lane >> 2);
            float b0 = bias ? bias[m0 + row] : 0.f;
            float b1 = bias ? bias[m0 + row + 8] : 0.f;
#pragma unroll
            for (int ni = 0; ni < 8; ni++) {
                int col = wc*64 + ni*8 + (lane & 3) * 2;
                *(float2*)&Ef[row * ELDF + col] =
                    make_float2(acc[mi][ni][0] + b0, acc[mi][ni][1] + b0);
                *(float2*)&Ef[(row + 8) * ELDF + col] =
                    make_float2(acc[mi][ni][2] + b1, acc[mi][ni][3] + b1);
            }
        }
        __syncthreads();
#pragma unroll
        for (int u = 0; u < 16; u++) {
            int linear = tid + u * 256;
            int row = linear >> 5, c4 = (linear & 31) * 4;
            *(float4*)&Cp[(size_t)(m0 + row) * P + n0 + c4] =
                *(const float4*)&Ef[row * ELDF + c4];
        }
    } else {
        // staged bf16 epilogue (hi/lo), uint4 coalesced stores
        __nv_bfloat16* Eh = (__nv_bfloat16*)sm;                  // 128 x ELD
        __nv_bfloat16* El = (__nv_bfloat16*)(sm + 128 * ELD * 2);
#pragma unroll
        for (int mi = 0; mi < 2; mi++) {
            int row = wr*32 + mi*16 + (lane >> 2);
#pragma unroll
            for (int ni = 0; ni < 8; ni++) {
                int col = wc*64 + ni*8 + (lane & 3) * 2;
                put_hl2(Eh, El, row * ELD + col, acc[mi][ni][0], acc[mi][ni][1]);
                put_hl2(Eh, El, (row + 8) * ELD + col, acc[mi][ni][2], acc[mi][ni][3]);
            }
        }
        __syncthreads();
        __nv_bfloat16* Chz = Ch + (size_t)blockIdx.z * Mtot * P;
        __nv_bfloat16* Clz = Cl + (size_t)blockIdx.z * Mtot * P;
#pragma unroll
        for (int u = 0; u < 8; u++) {
            int linear = tid + u * 256;
            int row = linear >> 4, c8 = (linear & 15) * 8;
            size_t go = (size_t)(m0 + row) * P + n0 + c8;
            *(uint4*)&Chz[go] = *(const uint4*)&Eh[row * ELD + c8];
            *(uint4*)&Clz[go] = *(const uint4*)&El[row * ELD + c8];
        }
    }
}

// ---------------- fused attention v5 (unchanged from R10) ----------------
#define QLD4 72
#define KLD4 264
#define PLD4 264
#define OLD4 65
#define AQH4 0
#define AQL4 9216
#define AKH4 18432
#define AKL4 52224
#define AVH4 86016
#define AVL4 119808
#define APH4 153600
#define APL4 187392
#define AREDM 221184
#define AREDS 222208
#define ATT_SM4 223232

__global__ __launch_bounds__(512)
void mm_attn4()
{
    extern __shared__ char sm[];
    uint32_t sb = smem_u32(sm);
    float* red_m = (float*)(sm + AREDM);
    float* red_s = (float*)(sm + AREDS);
    float* O   = (float*)(sm + APH4);
    __nv_bfloat16* Ph = (__nv_bfloat16*)(sm + APH4);
    __nv_bfloat16* Pl = (__nv_bfloat16*)(sm + APL4);

    int tid = threadIdx.x, lane = tid & 31, wid = tid >> 5;
    int bh = blockIdx.x, dir = blockIdx.y;
    int b = bh >> 3, h = bh & 7;
    int qin = dir, kin = dir ^ 1;
    int wr = wid >> 2, wc = wid & 3;

    const __nv_bfloat16* qh = &g_q_h[qin][b][0][0];
    const __nv_bfloat16* ql = &g_q_l[qin][b][0][0];
    const __nv_bfloat16* kh = &g_kv_h[kin][b][0][0];
    const __nv_bfloat16* kl = &g_kv_l[kin][b][0][0];

    int qhalf = tid >> 8, qt = tid & 255;
    int qd = qt >> 2, qch = (qt & 3) * 16;
    const __nv_bfloat16* qsrc = (qhalf ? ql : qh) + (size_t)(h * 64 + qd) * NP1 + qch;
    uint32_t qdst = sb + (qhalf ? AQL4 : AQH4) + (uint32_t)(qd * QLD4 + qch) * 2;

#pragma unroll
    for (int u = 0; u < 4; u++) {
        int idx = tid + u * 512;
        int d = idx >> 5, ch = (idx & 31) * 8;
        size_t gk = (size_t)(h * 64 + d) * NP2 + ch;
        size_t gv = (size_t)(NINNER + h * 64 + d) * NP2 + ch;
        uint32_t so = (uint32_t)(d * KLD4 + ch) * 2;
        cpa16(sb + AKH4 + so, kh + gk);
        cpa16(sb + AKL4 + so, kl + gk);
        cpa16(sb + AVH4 + so, kh + gv);
        cpa16(sb + AVL4 + so, kl + gv);
    }
    cpa16(qdst, qsrc);
    cpa16(qdst + 16, qsrc + 8);
    CP_COMMIT();

    int rA = wr * 16 + (lane >> 2);
    int rB = rA + 8;

    for (int it = 0; it < 16; it++) {
        CP_WAIT0();
        __syncthreads();
        int i0 = it * 64;

        float acc[8][4];
#pragma unroll
        for (int i = 0; i < 8; i++)
#pragma unroll
            for (int k = 0; k < 4; k++) acc[i][k] = 0.f;

#pragma unroll
        for (int kk = 0; kk < 4; kk++) {
            uint32_t ah[4], al[4];
            uint32_t krow = (uint32_t)(kk*16 + (lane & 7) + ((lane >> 1) & 8));
            uint32_t acol = (uint32_t)(wr*16 + (lane & 8));
            uint32_t aaddr = sb + AQH4 + (krow * QLD4 + acol) * 2;
            ldmx4t(ah, aaddr);
            ldmx4t(al, aaddr + (AQL4 - AQH4));
#pragma unroll
            for (int ni2 = 0; ni2 < 4; ni2++) {
                uint32_t bhf[4], blf[4];
                uint32_t baddr = sb + AKH4 + (uint32_t)((kk*16 + (lane & 15)) * KLD4
                                                        + wc*64 + ni2*16 + ((lane & 16) >> 1)) * 2;
                ldmx4t(bhf, baddr);
                ldmx4t(blf, baddr + (AKL4 - AKH4));
                mma16816(acc[ni2*2],   ah, &bhf[0]);
                mma16816(acc[ni2*2],   ah, &blf[0]);
                mma16816(acc[ni2*2],   al, &bhf[0]);
                mma16816(acc[ni2*2+1], ah, &bhf[2]);
                mma16816(acc[ni2*2+1], ah, &blf[2]);
                mma16816(acc[ni2*2+1], al, &bhf[2]);
            }
        }
        __syncthreads();

        if (it + 1 < 16) {
            const __nv_bfloat16* nq = qsrc + (it + 1) * 64;
            cpa16(qdst, nq);
            cpa16(qdst + 16, nq + 8);
            CP_COMMIT();
        }

#pragma unroll
        for (int ni = 0; ni < 8; ni++)
#pragma unroll
            for (int k = 0; k < 4; k++) acc[ni][k] *= 0.125f;

        float mA = -1e30f, mB = -1e30f;
#pragma unroll
        for (int ni = 0; ni < 8; ni++) {
            mA = fmaxf(mA, fmaxf(acc[ni][0], acc[ni][1]));
            mB = fmaxf(mB, fmaxf(acc[ni][2], acc[ni][3]));
        }
        mA = fmaxf(mA, __shfl_xor_sync(0xffffffffu, mA, 1));
        mA = fmaxf(mA, __shfl_xor_sync(0xffffffffu, mA, 2));
        mB = fmaxf(mB, __shfl_xor_sync(0xffffffffu, mB, 1));
        mB = fmaxf(mB, __shfl_xor_sync(0xffffffffu, mB, 2));
        if ((lane & 3) == 0) { red_m[rA * 4 + wc] = mA; red_m[rB * 4 + wc] = mB; }
        __syncthreads();
        mA = fmaxf(fmaxf(red_m[rA*4], red_m[rA*4+1]), fmaxf(red_m[rA*4+2], red_m[rA*4+3]));
        mB = fmaxf(fmaxf(red_m[rB*4], red_m[rB*4+1]), fmaxf(red_m[rB*4+2], red_m[rB*4+3]));

        float sA = 0.f, sB = 0.f;
#pragma unroll
        for (int ni = 0; ni < 8; ni++) {
            acc[ni][0] = __expf(acc[ni][0] - mA);
            acc[ni][1] = __expf(acc[ni][1] - mA);
            acc[ni][2] = __expf(acc[ni][2] - mB);
            acc[ni][3] = __expf(acc[ni][3] - mB);
            sA += acc[ni][0] + acc[ni][1];
            sB += acc[ni][2] + acc[ni][3];
        }
        sA += __shfl_xor_sync(0xffffffffu, sA, 1);
        sA += __shfl_xor_sync(0xffffffffu, sA, 2);
        sB += __shfl_xor_sync(0xffffffffu, sB, 1);
        sB += __shfl_xor_sync(0xffffffffu, sB, 2);
        if ((lane & 3) == 0) { red_s[rA * 4 + wc] = sA; red_s[rB * 4 + wc] = sB; }
        __syncthreads();
        float invA = 1.f / (red_s[rA*4] + red_s[rA*4+1] + red_s[rA*4+2] + red_s[rA*4+3]);
        float invB = 1.f / (red_s[rB*4] + red_s[rB*4+1] + red_s[rB*4+2] + red_s[rB*4+3]);

#pragma unroll
        for (int ni = 0; ni < 8; ni++) {
            int c = wc*64 + ni*8 + (lane & 3) * 2;
            put_hl2(Ph, Pl, rA * PLD4 + c, acc[ni][0] * invA, acc[ni][1] * invA);
            put_hl2(Ph, Pl, rB * PLD4 + c, acc[ni][2] * invB, acc[ni][3] * invB);
        }
        __syncthreads();

        float acc2[2][4];
#pragma unroll
        for (int i = 0; i < 2; i++)
#pragma unroll
            for (int k = 0; k < 4; k++) acc2[i][k] = 0.f;

#pragma unroll 4
        for (int kk = 0; kk < 16; kk++) {
            uint32_t ah[4], al[4];
            uint32_t aaddr = sb + APH4 + (uint32_t)((wr*16 + (lane & 15)) * PLD4
                                                    + kk*16 + (lane >> 4) * 8) * 2;
            ldmx4(ah, aaddr);
            ldmx4(al, aaddr + (APL4 - APH4));
            uint32_t bhf[4], blf[4];
            uint32_t baddr = sb + AVH4 + (uint32_t)((wc*16 + ((lane >> 4) & 1) * 8 + (lane & 7)) * KLD4
                                                    + kk*16 + ((lane >> 3) & 1) * 8) * 2;
            ldmx4(bhf, baddr);
            ldmx4(blf, baddr + (AVL4 - AVH4));
            mma16816(acc2[0], ah, &bhf[0]);
            mma16816(acc2[0], ah, &blf[0]);
            mma16816(acc2[0], al, &bhf[0]);
            mma16816(acc2[1], ah, &bhf[2]);
            mma16816(acc2[1], ah, &blf[2]);
            mma16816(acc2[1], al, &bhf[2]);
        }
        __syncthreads();

#pragma unroll
        for (int ni = 0; ni < 2; ni++) {
            int c = wc*16 + ni*8 + (lane & 3) * 2;
            O[rA * OLD4 + c]     = acc2[ni][0];
            O[rA * OLD4 + c + 1] = acc2[ni][1];
            O[rB * OLD4 + c]     = acc2[ni][2];
            O[rB * OLD4 + c + 1] = acc2[ni][3];
        }
        __syncthreads();
        {
            int d = tid >> 3, ip = (tid & 7) * 8;
            __nv_bfloat16* aoh = &g_ao_h[qin][b][h * 64 + d][i0 + ip];
            __nv_bfloat16* aol = &g_ao_l[qin][b][h * 64 + d][i0 + ip];
#pragma unroll
            for (int u = 0; u < 8; u += 2) {
                float v0 = O[(ip + u) * OLD4 + d];
                float v1 = O[(ip + u + 1) * OLD4 + d];
                put_hl2(aoh, aol, u, v0, v1);
            }
        }
    }
}

// ---------------- launch ----------------
extern "C" void kernel_launch(void* const* d_in, const int* in_sizes, int n_in,
                              void* d_out, int out_size)
{
    const float* x      = (const float*)d_in[0];
    const float* y      = (const float*)d_in[1];
    const float* q_dw_w = (const float*)d_in[2];
    const float* q_g    = (const float*)d_in[3];
    const float* q_b    = (const float*)d_in[4];
    const float* q_m    = (const float*)d_in[5];
    const float* q_v    = (const float*)d_in[6];
    const float* q_pw   = (const float*)d_in[7];
    const float* kv_dw_w= (const float*)d_in[8];
    const float* kv_g   = (const float*)d_in[9];
    const float* kv_b   = (const float*)d_in[10];
    const float* kv_m   = (const float*)d_in[11];
    const float* kv_v   = (const float*)d_in[12];
    const float* kv_pw  = (const float*)d_in[13];
    const float* out_w  = (const float*)d_in[14];
    const float* out_b  = (const float*)d_in[15];
    float* out = (float*)d_out;

    __nv_bfloat16 *wq_h, *wq_l, *wkv_h, *wkv_l, *wo_h, *wo_l;
    __nv_bfloat16 *hq_h, *hq_l, *hkv_h, *hkv_l, *q_hp, *q_lp, *kv_hp, *kv_lp, *ao_h, *ao_l;
    cudaGetSymbolAddress((void**)&wq_h,  g_wq_h);  cudaGetSymbolAddress((void**)&wq_l,  g_wq_l);
    cudaGetSymbolAddress((void**)&wkv_h, g_wkv_h); cudaGetSymbolAddress((void**)&wkv_l, g_wkv_l);
    cudaGetSymbolAddress((void**)&wo_h,  g_wo_h);  cudaGetSymbolAddress((void**)&wo_l,  g_wo_l);
    cudaGetSymbolAddress((void**)&hq_h,  g_hq_h);  cudaGetSymbolAddress((void**)&hq_l,  g_hq_l);
    cudaGetSymbolAddress((void**)&hkv_h, g_hkv_h); cudaGetSymbolAddress((void**)&hkv_l, g_hkv_l);
    cudaGetSymbolAddress((void**)&q_hp,  g_q_h);   cudaGetSymbolAddress((void**)&q_lp,  g_q_l);
    cudaGetSymbolAddress((void**)&kv_hp, g_kv_h);  cudaGetSymbolAddress((void**)&kv_lp, g_kv_l);
    cudaGetSymbolAddress((void**)&ao_h,  g_ao_h);  cudaGetSymbolAddress((void**)&ao_l,  g_ao_l);

    static cudaStream_t s1 = nullptr;
    static cudaEvent_t e_fork, e_cvt, e_dw, e_kv;
    if (!s1) {
        cudaStreamCreateWithFlags(&s1, cudaStreamNonBlocking);
        cudaEventCreateWithFlags(&e_fork, cudaEventDisableTiming);
        cudaEventCreateWithFlags(&e_cvt,  cudaEventDisableTiming);
        cudaEventCreateWithFlags(&e_dw,   cudaEventDisableTiming);
        cudaEventCreateWithFlags(&e_kv,   cudaEventDisableTiming);
        cudaFuncSetAttribute(mm_attn4, cudaFuncAttributeMaxDynamicSharedMemorySize, ATT_SM4);
        cudaFuncSetAttribute(mm_gemm2, cudaFuncAttributeMaxDynamicSharedMemorySize, GSM3);
    }

    cudaEventRecord(e_fork, 0);
    cudaStreamWaitEvent(s1, e_fork, 0);

    cvt_hl_kernel<<<(NINNER * NC / 2 + 255) / 256, 256, 0, s1>>>(q_pw,  wq_h,  wq_l,  NINNER * NC / 2);
    cvt_hl_kernel<<<(2 * NINNER * NC / 2 + 255) / 256, 256, 0, s1>>>(kv_pw, wkv_h, wkv_l, 2 * NINNER * NC / 2);
    cvt_hl_kernel<<<(NC * NINNER / 2 + 255) / 256, 256, 0, s1>>>(out_w, wo_h,  wo_l,  NC * NINNER / 2);
    cudaEventRecord(e_cvt, s1);

    dwbn_fused<<<dim3(NB * NC, 2), 256>>>(x, y,
        q_dw_w, q_g, q_b, q_m, q_v,
        kv_dw_w, kv_g, kv_b, kv_m, kv_v);
    cudaEventRecord(e_dw, 0);

    cudaStreamWaitEvent(s1, e_dw, 0);
    mm_gemm2<<<dim3(NP2 / 128, (2 * NINNER) / 128, 2 * NB), 256, GSM3, s1>>>(
        wkv_h, wkv_l, hkv_h, hkv_l, kv_hp, kv_lp, nullptr, nullptr,
        2 * NINNER, NC, NP2);
    cudaEventRecord(e_kv, s1);

    cudaStreamWaitEvent(0, e_cvt, 0);
    mm_gemm2<<<dim3(NP1 / 128, NINNER / 128, 2 * NB), 256, GSM3>>>(
        wq_h, wq_l, hq_h, hq_l, q_hp, q_lp, nullptr, nullptr,
        NINNER, NC, NP1);

    cudaStreamWaitEvent(0, e_kv, 0);
    mm_attn4<<<dim3(2 * NB * 8 / 2, 2), 512, ATT_SM4>>>();

    mm_gemm2<<<dim3(NP1 / 128, NC / 128, 2 * NB), 256, GSM3>>>(
        wo_h, wo_l, ao_h, ao_l, nullptr, nullptr, out, out_b,
        NC, NINNER, NP1);
}

// round 12
// speedup vs baseline: 1.0118x; 1.0118x over previous
#include <cuda_runtime.h>
#include <cuda_bf16.h>
#include <stdint.h>
#include <math.h>

#define NB 8
#define NC 256
#define NP1 1024
#define NP2 256
#define NINNER 512
#define BN_EPS 1e-5f

// ---------------- bf16 hi/lo scratch ----------------
__device__ __nv_bfloat16 g_hq_h [2][NB][NC][NP1],      g_hq_l [2][NB][NC][NP1];
__device__ __nv_bfloat16 g_hkv_h[2][NB][NC][NP2],      g_hkv_l[2][NB][NC][NP2];
__device__ __nv_bfloat16 g_q_h  [2][NB][NINNER][NP1],  g_q_l  [2][NB][NINNER][NP1];
__device__ __nv_bfloat16 g_kv_h [2][NB][2*NINNER][NP2],g_kv_l [2][NB][2*NINNER][NP2];
__device__ __nv_bfloat16 g_ao_h [2][NB][NINNER][NP1],  g_ao_l [2][NB][NINNER][NP1];
__device__ __nv_bfloat16 g_wq_h [NINNER*NC],   g_wq_l [NINNER*NC];
__device__ __nv_bfloat16 g_wkv_h[2*NINNER*NC], g_wkv_l[2*NINNER*NC];
__device__ __nv_bfloat16 g_wo_h [NC*NINNER],   g_wo_l [NC*NINNER];

// ---------------- helpers ----------------
__device__ __forceinline__ uint32_t smem_u32(const void* p){
    uint32_t a;
    asm("{ .reg .u64 t; cvta.to.shared.u64 t, %1; cvt.u32.u64 %0, t; }" : "=r"(a) : "l"(p));
    return a;
}
__device__ __forceinline__ void ldmx4(uint32_t* r, uint32_t a){
    asm volatile("ldmatrix.sync.aligned.m8n8.x4.shared.b16 {%0,%1,%2,%3}, [%4];"
        : "=r"(r[0]),"=r"(r[1]),"=r"(r[2]),"=r"(r[3]) : "r"(a) : "memory");
}
__device__ __forceinline__ void ldmx4t(uint32_t* r, uint32_t a){
    asm volatile("ldmatrix.sync.aligned.m8n8.x4.trans.shared.b16 {%0,%1,%2,%3}, [%4];"
        : "=r"(r[0]),"=r"(r[1]),"=r"(r[2]),"=r"(r[3]) : "r"(a) : "memory");
}
__device__ __forceinline__ void mma16816(float* c, const uint32_t* a, const uint32_t* b){
    asm volatile("mma.sync.aligned.m16n8k16.row.col.f32.bf16.bf16.f32 "
        "{%0,%1,%2,%3}, {%4,%5,%6,%7}, {%8,%9}, {%0,%1,%2,%3};"
        : "+f"(c[0]),"+f"(c[1]),"+f"(c[2]),"+f"(c[3])
        : "r"(a[0]),"r"(a[1]),"r"(a[2]),"r"(a[3]),"r"(b[0]),"r"(b[1]));
}
__device__ __forceinline__ void cpa16(uint32_t s, const void* g){
    asm volatile("cp.async.cg.shared.global [%0], [%1], 16;" :: "r"(s), "l"(g));
}
#define CP_COMMIT() asm volatile("cp.async.commit_group;" ::: "memory")
#define CP_WAIT0()  asm volatile("cp.async.wait_group 0;" ::: "memory")
#define CP_WAIT1()  asm volatile("cp.async.wait_group 1;" ::: "memory")

__device__ __forceinline__ void put_hl(__nv_bfloat16* bh, __nv_bfloat16* bl, int idx, float v){
    __nv_bfloat16 h = __float2bfloat16(v);
    bh[idx] = h;
    bl[idx] = __float2bfloat16(v - __bfloat162float(h));
}
__device__ __forceinline__ void put_hl2(__nv_bfloat16* bh, __nv_bfloat16* bl, int idx, float v0, float v1){
    __nv_bfloat16 h0 = __float2bfloat16(v0), h1 = __float2bfloat16(v1);
    __nv_bfloat162 H; H.x = h0; H.y = h1;
    __nv_bfloat162 L;
    L.x = __float2bfloat16(v0 - __bfloat162float(h0));
    L.y = __float2bfloat16(v1 - __bfloat162float(h1));
    *(__nv_bfloat162*)(bh + idx) = H;
    *(__nv_bfloat162*)(bl + idx) = L;
}

// ---------------- weight fp32 -> hi/lo ----------------
__global__ void cvt_hl_kernel(const float* __restrict__ src, __nv_bfloat16* __restrict__ h,
                              __nv_bfloat16* __restrict__ l, int n2){
    int i = blockIdx.x * 256 + threadIdx.x;
    if (i < n2) {
        float2 v = *(const float2*)(src + i * 2);
        put_hl2(h, l, i * 2, v.x, v.y);
    }
}

// ---------------- fused depthwise conv (s1 + s2) + BN -> bf16 hi/lo ----------------
__global__ __launch_bounds__(256)
void dwbn_fused(const float* __restrict__ x0, const float* __restrict__ x1,
                const float* __restrict__ qw, const float* __restrict__ qg,
                const float* __restrict__ qb, const float* __restrict__ qm,
                const float* __restrict__ qv,
                const float* __restrict__ kw, const float* __restrict__ kg,
                const float* __restrict__ kb, const float* __restrict__ km,
                const float* __restrict__ kvv)
{
    int inp = blockIdx.y, bc = blockIdx.x, c = bc & 255, b = bc >> 8;
    const float* in = (inp ? x1 : x0) + (size_t)bc * 1024;
    __shared__ float t[34][36];
    int tid = threadIdx.x;

    if (tid < 34) { t[0][tid] = 0.f; t[33][tid] = 0.f; }
    else if (tid < 66) { int r = tid - 33; t[r][0] = 0.f; t[r][33] = 0.f; }

    {
        int r = tid >> 3, q = (tid & 7) * 4;
        float4 v = *(const float4*)(in + r * 32 + q);
        t[r + 1][q + 1] = v.x; t[r + 1][q + 2] = v.y;
        t[r + 1][q + 3] = v.z; t[r + 1][q + 4] = v.w;
    }

    float qwr[9], kwr[9];
#pragma unroll
    for (int i = 0; i < 9; i++) { qwr[i] = qw[c * 9 + i]; kwr[i] = kw[c * 9 + i]; }
    float qs  = qg[c] * rsqrtf(qv[c] + BN_EPS);
    float qsh = qb[c] - qm[c] * qs;
    float ks  = kg[c] * rsqrtf(kvv[c] + BN_EPS);
    float ksh = kb[c] - km[c] * ks;
    __syncthreads();

    {
        int oy = tid >> 3, ox = (tid & 7) * 4;
        float o0 = 0.f, o1 = 0.f, o2 = 0.f, o3 = 0.f;
#pragma unroll
        for (int dy = 0; dy < 3; dy++) {
            float a0 = t[oy + dy][ox + 0], a1 = t[oy + dy][ox + 1], a2 = t[oy + dy][ox + 2];
            float a3 = t[oy + dy][ox + 3], a4 = t[oy + dy][ox + 4], a5 = t[oy + dy][ox + 5];
            float w0 = qwr[dy * 3], w1 = qwr[dy * 3 + 1], w2 = qwr[dy * 3 + 2];
            o0 += a0 * w0 + a1 * w1 + a2 * w2;
            o1 += a1 * w0 + a2 * w1 + a3 * w2;
            o2 += a2 * w0 + a3 * w1 + a4 * w2;
            o3 += a3 * w0 + a4 * w1 + a5 * w2;
        }
        o0 = o0 * qs + qsh; o1 = o1 * qs + qsh;
        o2 = o2 * qs + qsh; o3 = o3 * qs + qsh;
        int idx = oy * 32 + ox;
        put_hl2(&g_hq_h[inp][b][c][0], &g_hq_l[inp][b][c][0], idx, o0, o1);
        put_hl2(&g_hq_h[inp][b][c][0], &g_hq_l[inp][b][c][0], idx + 2, o2, o3);
    }

    {
        int oy = tid >> 4, ox = tid & 15;
        float a = 0.f;
#pragma unroll
        for (int dy = 0; dy < 3; dy++)
#pragma unroll
            for (int dx = 0; dx < 3; dx++)
                a += t[oy * 2 + dy][ox * 2 + dx] * kwr[dy * 3 + dx];
        a = a * ks + ksh;
        put_hl(&g_hkv_h[inp][b][c][0], &g_hkv_l[inp][b][c][0], oy * 16 + ox, a);
    }
}

// ---------------- tensor-core GEMM (R10 config: 2-stage, 2 CTAs/SM) ----------------
#define ALD2 40
#define BLD2 136
#define A_H0 0
#define A_H1 10240
#define A_L0 20480
#define A_L1 30720
#define B_H0 40960
#define B_H1 49664
#define B_L0 58368
#define B_L1 67072
#define GSM2 75776
#define ELD 136          // bf16 epilogue stage LD
#define ELDF 136         // fp32 epilogue stage LD (floats)

__global__ __launch_bounds__(256, 2)
void mm_gemm2(const __nv_bfloat16* __restrict__ Ah, const __nv_bfloat16* __restrict__ Al,
              const __nv_bfloat16* __restrict__ Bh, const __nv_bfloat16* __restrict__ Bl,
              __nv_bfloat16* __restrict__ Ch, __nv_bfloat16* __restrict__ Cl,
              float* __restrict__ Cf, const float* __restrict__ bias,
              int Mtot, int K, int P)
{
    extern __shared__ char sm[];
    uint32_t sb = smem_u32(sm);
    int tid = threadIdx.x, lane = tid & 31, wid = tid >> 5;
    int wr = wid >> 1, wc = wid & 1;
    int m0 = blockIdx.y * 128, n0 = blockIdx.x * 128;
    size_t zoff = (size_t)blockIdx.z * K * P;
    const __nv_bfloat16* Bhz = Bh + zoff;
    const __nv_bfloat16* Blz = Bl + zoff;

    float acc[2][8][4];
#pragma unroll
    for (int i = 0; i < 2; i++)
#pragma unroll
        for (int j = 0; j < 8; j++)
#pragma unroll
            for (int k = 0; k < 4; k++) acc[i][j][k] = 0.f;

    int niter = K >> 5;

#define LOAD_STAGE(st, k0) do { \
    uint32_t aH = sb + ((st) ? A_H1 : A_H0); \
    uint32_t aL = sb + ((st) ? A_L1 : A_L0); \
    uint32_t bH = sb + ((st) ? B_H1 : B_H0); \
    uint32_t bL = sb + ((st) ? B_L1 : B_L0); \
    _Pragma("unroll") \
    for (int u = 0; u < 2; u++) { \
        int idx = tid + u * 256; \
        int row = idx >> 2, ch = (idx & 3) * 8; \
        size_t go = (size_t)(m0 + row) * K + (k0) + ch; \
        uint32_t so = (uint32_t)(row * ALD2 + ch) * 2; \
        cpa16(aH + so, Ah + go); \
        cpa16(aL + so, Al + go); \
    } \
    _Pragma("unroll") \
    for (int u = 0; u < 2; u++) { \
        int idx = tid + u * 256; \
        int row = idx >> 4, ch = (idx & 15) * 8; \
        size_t go = (size_t)((k0) + row) * P + n0 + ch; \
        uint32_t so = (uint32_t)(row * BLD2 + ch) * 2; \
        cpa16(bH + so, Bhz + go); \
        cpa16(bL + so, Blz + go); \
    } \
} while (0)

    LOAD_STAGE(0, 0);
    CP_COMMIT();

    for (int it = 0; it < niter; it++) {
        if (it + 1 < niter) { LOAD_STAGE((it + 1) & 1, (it + 1) << 5); CP_COMMIT(); CP_WAIT1(); }
        else CP_WAIT0();
        __syncthreads();

        uint32_t aHb = sb + ((it & 1) ? A_H1 : A_H0);
        uint32_t bHb = sb + ((it & 1) ? B_H1 : B_H0);
#pragma unroll
        for (int kk = 0; kk < 2; kk++) {
            uint32_t ah[2][4], al[2][4];
#pragma unroll
            for (int mi = 0; mi < 2; mi++) {
                uint32_t aaddr = aHb + (uint32_t)((wr*32 + mi*16 + (lane & 15)) * ALD2
                                                  + kk*16 + (lane >> 4) * 8) * 2;
                ldmx4(ah[mi], aaddr);
                ldmx4(al[mi], aaddr + 20480u);
            }
#pragma unroll
            for (int ni2 = 0; ni2 < 4; ni2++) {
                uint32_t bh[4], bl[4];
                uint32_t baddr = bHb + (uint32_t)((kk*16 + (lane & 15)) * BLD2
                                                  + wc*64 + ni2*16 + ((lane & 16) >> 1)) * 2;
                ldmx4t(bh, baddr);
                ldmx4t(bl, baddr + 17408u);
#pragma unroll
                for (int mi = 0; mi < 2; mi++) {
                    mma16816(acc[mi][ni2*2],   ah[mi], &bh[0]);
                    mma16816(acc[mi][ni2*2],   ah[mi], &bl[0]);
                    mma16816(acc[mi][ni2*2],   al[mi], &bh[0]);
                    mma16816(acc[mi][ni2*2+1], ah[mi], &bh[2]);
                    mma16816(acc[mi][ni2*2+1], ah[mi], &bl[2]);
                    mma16816(acc[mi][ni2*2+1], al[mi], &bh[2]);
                }
            }
        }
        __syncthreads();
    }

    if (Cf) {
        // staged fp32 epilogue: fragments(+bias) -> smem, then coalesced float4 stores
        float* Ef = (float*)sm;   // 128 x ELDF floats = 69632 B < GSM2
        float* Cp = Cf + (size_t)blockIdx.z * Mtot * P;
#pragma unroll
        for (int mi = 0; mi < 2; mi++) {
            int row = wr*32 + mi*16 + (lane >> 2);
            float b0 = bias ? bias[m0 + row] : 0.f;
            float b1 = bias ? bias[m0 + row + 8] : 0.f;
#pragma unroll
            for (int ni = 0; ni < 8; ni++) {
                int col = wc*64 + ni*8 + (lane & 3) * 2;
                *(float2*)&Ef[row * ELDF + col] =
                    make_float2(acc[mi][ni][0] + b0, acc[mi][ni][1] + b0);
                *(float2*)&Ef[(row + 8) * ELDF + col] =
                    make_float2(acc[mi][ni][2] + b1, acc[mi][ni][3] + b1);
            }
        }
        __syncthreads();
#pragma unroll
        for (int u = 0; u < 16; u++) {
            int linear = tid + u * 256;
            int row = linear >> 5, c4 = (linear & 31) * 4;
            *(float4*)&Cp[(size_t)(m0 + row) * P + n0 + c4] =
                *(const float4*)&Ef[row * ELDF + c4];
        }
    } else {
        // staged bf16 epilogue (hi/lo), uint4 coalesced stores
        __nv_bfloat16* Eh = (__nv_bfloat16*)sm;                  // 128 x ELD
        __nv_bfloat16* El = (__nv_bfloat16*)(sm + 128 * ELD * 2);
#pragma unroll
        for (int mi = 0; mi < 2; mi++) {
            int row = wr*32 + mi*16 + (lane >> 2);
#pragma unroll
            for (int ni = 0; ni < 8; ni++) {
                int col = wc*64 + ni*8 + (lane & 3) * 2;
                put_hl2(Eh, El, row * ELD + col, acc[mi][ni][0], acc[mi][ni][1]);
                put_hl2(Eh, El, (row + 8) * ELD + col, acc[mi][ni][2], acc[mi][ni][3]);
            }
        }
        __syncthreads();
        __nv_bfloat16* Chz = Ch + (size_t)blockIdx.z * Mtot * P;
        __nv_bfloat16* Clz = Cl + (size_t)blockIdx.z * Mtot * P;
#pragma unroll
        for (int u = 0; u < 8; u++) {
            int linear = tid + u * 256;
            int row = linear >> 4, c8 = (linear & 15) * 8;
            size_t go = (size_t)(m0 + row) * P + n0 + c8;
            *(uint4*)&Chz[go] = *(const uint4*)&Eh[row * ELD + c8];
            *(uint4*)&Clz[go] = *(const uint4*)&El[row * ELD + c8];
        }
    }
}

// ---------------- fused attention v5 (unchanged from R10) ----------------
#define QLD4 72
#define KLD4 264
#define PLD4 264
#define OLD4 65
#define AQH4 0
#define AQL4 9216
#define AKH4 18432
#define AKL4 52224
#define AVH4 86016
#define AVL4 119808
#define APH4 153600
#define APL4 187392
#define AREDM 221184
#define AREDS 222208
#define ATT_SM4 223232

__global__ __launch_bounds__(512)
void mm_attn4()
{
    extern __shared__ char sm[];
    uint32_t sb = smem_u32(sm);
    float* red_m = (float*)(sm + AREDM);
    float* red_s = (float*)(sm + AREDS);
    float* O   = (float*)(sm + APH4);
    __nv_bfloat16* Ph = (__nv_bfloat16*)(sm + APH4);
    __nv_bfloat16* Pl = (__nv_bfloat16*)(sm + APL4);

    int tid = threadIdx.x, lane = tid & 31, wid = tid >> 5;
    int bh = blockIdx.x, dir = blockIdx.y;
    int b = bh >> 3, h = bh & 7;
    int qin = dir, kin = dir ^ 1;
    int wr = wid >> 2, wc = wid & 3;

    const __nv_bfloat16* qh = &g_q_h[qin][b][0][0];
    const __nv_bfloat16* ql = &g_q_l[qin][b][0][0];
    const __nv_bfloat16* kh = &g_kv_h[kin][b][0][0];
    const __nv_bfloat16* kl = &g_kv_l[kin][b][0][0];

    int qhalf = tid >> 8, qt = tid & 255;
    int qd = qt >> 2, qch = (qt & 3) * 16;
    const __nv_bfloat16* qsrc = (qhalf ? ql : qh) + (size_t)(h * 64 + qd) * NP1 + qch;
    uint32_t qdst = sb + (qhalf ? AQL4 : AQH4) + (uint32_t)(qd * QLD4 + qch) * 2;

#pragma unroll
    for (int u = 0; u < 4; u++) {
        int idx = tid + u * 512;
        int d = idx >> 5, ch = (idx & 31) * 8;
        size_t gk = (size_t)(h * 64 + d) * NP2 + ch;
        size_t gv = (size_t)(NINNER + h * 64 + d) * NP2 + ch;
        uint32_t so = (uint32_t)(d * KLD4 + ch) * 2;
        cpa16(sb + AKH4 + so, kh + gk);
        cpa16(sb + AKL4 + so, kl + gk);
        cpa16(sb + AVH4 + so, kh + gv);
        cpa16(sb + AVL4 + so, kl + gv);
    }
    cpa16(qdst, qsrc);
    cpa16(qdst + 16, qsrc + 8);
    CP_COMMIT();

    int rA = wr * 16 + (lane >> 2);
    int rB = rA + 8;

    for (int it = 0; it < 16; it++) {
        CP_WAIT0();
        __syncthreads();
        int i0 = it * 64;

        float acc[8][4];
#pragma unroll
        for (int i = 0; i < 8; i++)
#pragma unroll
            for (int k = 0; k < 4; k++) acc[i][k] = 0.f;

#pragma unroll
        for (int kk = 0; kk < 4; kk++) {
            uint32_t ah[4], al[4];
            uint32_t krow = (uint32_t)(kk*16 + (lane & 7) + ((lane >> 1) & 8));
            uint32_t acol = (uint32_t)(wr*16 + (lane & 8));
            uint32_t aaddr = sb + AQH4 + (krow * QLD4 + acol) * 2;
            ldmx4t(ah, aaddr);
            ldmx4t(al, aaddr + (AQL4 - AQH4));
#pragma unroll
            for (int ni2 = 0; ni2 < 4; ni2++) {
                uint32_t bhf[4], blf[4];
                uint32_t baddr = sb + AKH4 + (uint32_t)((kk*16 + (lane & 15)) * KLD4
                                                        + wc*64 + ni2*16 + ((lane & 16) >> 1)) * 2;
                ldmx4t(bhf, baddr);
                ldmx4t(blf, baddr + (AKL4 - AKH4));
                mma16816(acc[ni2*2],   ah, &bhf[0]);
                mma16816(acc[ni2*2],   ah, &blf[0]);
                mma16816(acc[ni2*2],   al, &bhf[0]);
                mma16816(acc[ni2*2+1], ah, &bhf[2]);
                mma16816(acc[ni2*2+1], ah, &blf[2]);
                mma16816(acc[ni2*2+1], al, &bhf[2]);
            }
        }
        __syncthreads();

        if (it + 1 < 16) {
            const __nv_bfloat16* nq = qsrc + (it + 1) * 64;
            cpa16(qdst, nq);
            cpa16(qdst + 16, nq + 8);
            CP_COMMIT();
        }

#pragma unroll
        for (int ni = 0; ni < 8; ni++)
#pragma unroll
            for (int k = 0; k < 4; k++) acc[ni][k] *= 0.125f;

        float mA = -1e30f, mB = -1e30f;
#pragma unroll
        for (int ni = 0; ni < 8; ni++) {
            mA = fmaxf(mA, fmaxf(acc[ni][0], acc[ni][1]));
            mB = fmaxf(mB, fmaxf(acc[ni][2], acc[ni][3]));
        }
        mA = fmaxf(mA, __shfl_xor_sync(0xffffffffu, mA, 1));
        mA = fmaxf(mA, __shfl_xor_sync(0xffffffffu, mA, 2));
        mB = fmaxf(mB, __shfl_xor_sync(0xffffffffu, mB, 1));
        mB = fmaxf(mB, __shfl_xor_sync(0xffffffffu, mB, 2));
        if ((lane & 3) == 0) { red_m[rA * 4 + wc] = mA; red_m[rB * 4 + wc] = mB; }
        __syncthreads();
        mA = fmaxf(fmaxf(red_m[rA*4], red_m[rA*4+1]), fmaxf(red_m[rA*4+2], red_m[rA*4+3]));
        mB = fmaxf(fmaxf(red_m[rB*4], red_m[rB*4+1]), fmaxf(red_m[rB*4+2], red_m[rB*4+3]));

        float sA = 0.f, sB = 0.f;
#pragma unroll
        for (int ni = 0; ni < 8; ni++) {
            acc[ni][0] = __expf(acc[ni][0] - mA);
            acc[ni][1] = __expf(acc[ni][1] - mA);
            acc[ni][2] = __expf(acc[ni][2] - mB);
            acc[ni][3] = __expf(acc[ni][3] - mB);
            sA += acc[ni][0] + acc[ni][1];
            sB += acc[ni][2] + acc[ni][3];
        }
        sA += __shfl_xor_sync(0xffffffffu, sA, 1);
        sA += __shfl_xor_sync(0xffffffffu, sA, 2);
        sB += __shfl_xor_sync(0xffffffffu, sB, 1);
        sB += __shfl_xor_sync(0xffffffffu, sB, 2);
        if ((lane & 3) == 0) { red_s[rA * 4 + wc] = sA; red_s[rB * 4 + wc] = sB; }
        __syncthreads();
        float invA = 1.f / (red_s[rA*4] + red_s[rA*4+1] + red_s[rA*4+2] + red_s[rA*4+3]);
        float invB = 1.f / (red_s[rB*4] + red_s[rB*4+1] + red_s[rB*4+2] + red_s[rB*4+3]);

#pragma unroll
        for (int ni = 0; ni < 8; ni++) {
            int c = wc*64 + ni*8 + (lane & 3) * 2;
            put_hl2(Ph, Pl, rA * PLD4 + c, acc[ni][0] * invA, acc[ni][1] * invA);
            put_hl2(Ph, Pl, rB * PLD4 + c, acc[ni][2] * invB, acc[ni][3] * invB);
        }
        __syncthreads();

        float acc2[2][4];
#pragma unroll
        for (int i = 0; i < 2; i++)
#pragma unroll
            for (int k = 0; k < 4; k++) acc2[i][k] = 0.f;

#pragma unroll 4
        for (int kk = 0; kk < 16; kk++) {
            uint32_t ah[4], al[4];
            uint32_t aaddr = sb + APH4 + (uint32_t)((wr*16 + (lane & 15)) * PLD4
                                                    + kk*16 + (lane >> 4) * 8) * 2;
            ldmx4(ah, aaddr);
            ldmx4(al, aaddr + (APL4 - APH4));
            uint32_t bhf[4], blf[4];
            uint32_t baddr = sb + AVH4 + (uint32_t)((wc*16 + ((lane >> 4) & 1) * 8 + (lane & 7)) * KLD4
                                                    + kk*16 + ((lane >> 3) & 1) * 8) * 2;
            ldmx4(bhf, baddr);
            ldmx4(blf, baddr + (AVL4 - AVH4));
            mma16816(acc2[0], ah, &bhf[0]);
            mma16816(acc2[0], ah, &blf[0]);
            mma16816(acc2[0], al, &bhf[0]);
            mma16816(acc2[1], ah, &bhf[2]);
            mma16816(acc2[1], ah, &blf[2]);
            mma16816(acc2[1], al, &bhf[2]);
        }
        __syncthreads();

#pragma unroll
        for (int ni = 0; ni < 2; ni++) {
            int c = wc*16 + ni*8 + (lane & 3) * 2;
            O[rA * OLD4 + c]     = acc2[ni][0];
            O[rA * OLD4 + c + 1] = acc2[ni][1];
            O[rB * OLD4 + c]     = acc2[ni][2];
            O[rB * OLD4 + c + 1] = acc2[ni][3];
        }
        __syncthreads();
        {
            int d = tid >> 3, ip = (tid & 7) * 8;
            __nv_bfloat16* aoh = &g_ao_h[qin][b][h * 64 + d][i0 + ip];
            __nv_bfloat16* aol = &g_ao_l[qin][b][h * 64 + d][i0 + ip];
#pragma unroll
            for (int u = 0; u < 8; u += 2) {
                float v0 = O[(ip + u) * OLD4 + d];
                float v1 = O[(ip + u + 1) * OLD4 + d];
                put_hl2(aoh, aol, u, v0, v1);
            }
        }
    }
}

// ---------------- launch ----------------
extern "C" void kernel_launch(void* const* d_in, const int* in_sizes, int n_in,
                              void* d_out, int out_size)
{
    const float* x      = (const float*)d_in[0];
    const float* y      = (const float*)d_in[1];
    const float* q_dw_w = (const float*)d_in[2];
    const float* q_g    = (const float*)d_in[3];
    const float* q_b    = (const float*)d_in[4];
    const float* q_m    = (const float*)d_in[5];
    const float* q_v    = (const float*)d_in[6];
    const float* q_pw   = (const float*)d_in[7];
    const float* kv_dw_w= (const float*)d_in[8];
    const float* kv_g   = (const float*)d_in[9];
    const float* kv_b   = (const float*)d_in[10];
    const float* kv_m   = (const float*)d_in[11];
    const float* kv_v   = (const float*)d_in[12];
    const float* kv_pw  = (const float*)d_in[13];
    const float* out_w  = (const float*)d_in[14];
    const float* out_b  = (const float*)d_in[15];
    float* out = (float*)d_out;

    __nv_bfloat16 *wq_h, *wq_l, *wkv_h, *wkv_l, *wo_h, *wo_l;
    __nv_bfloat16 *hq_h, *hq_l, *hkv_h, *hkv_l, *q_hp, *q_lp, *kv_hp, *kv_lp, *ao_h, *ao_l;
    cudaGetSymbolAddress((void**)&wq_h,  g_wq_h);  cudaGetSymbolAddress((void**)&wq_l,  g_wq_l);
    cudaGetSymbolAddress((void**)&wkv_h, g_wkv_h); cudaGetSymbolAddress((void**)&wkv_l, g_wkv_l);
    cudaGetSymbolAddress((void**)&wo_h,  g_wo_h);  cudaGetSymbolAddress((void**)&wo_l,  g_wo_l);
    cudaGetSymbolAddress((void**)&hq_h,  g_hq_h);  cudaGetSymbolAddress((void**)&hq_l,  g_hq_l);
    cudaGetSymbolAddress((void**)&hkv_h, g_hkv_h); cudaGetSymbolAddress((void**)&hkv_l, g_hkv_l);
    cudaGetSymbolAddress((void**)&q_hp,  g_q_h);   cudaGetSymbolAddress((void**)&q_lp,  g_q_l);
    cudaGetSymbolAddress((void**)&kv_hp, g_kv_h);  cudaGetSymbolAddress((void**)&kv_lp, g_kv_l);
    cudaGetSymbolAddress((void**)&ao_h,  g_ao_h);  cudaGetSymbolAddress((void**)&ao_l,  g_ao_l);

    static cudaStream_t s1 = nullptr;
    static cudaEvent_t e_fork, e_cvt, e_dw, e_kv;
    if (!s1) {
        cudaStreamCreateWithFlags(&s1, cudaStreamNonBlocking);
        cudaEventCreateWithFlags(&e_fork, cudaEventDisableTiming);
        cudaEventCreateWithFlags(&e_cvt,  cudaEventDisableTiming);
        cudaEventCreateWithFlags(&e_dw,   cudaEventDisableTiming);
        cudaEventCreateWithFlags(&e_kv,   cudaEventDisableTiming);
        cudaFuncSetAttribute(mm_attn4, cudaFuncAttributeMaxDynamicSharedMemorySize, ATT_SM4);
        cudaFuncSetAttribute(mm_gemm2, cudaFuncAttributeMaxDynamicSharedMemorySize, GSM2);
    }

    cudaEventRecord(e_fork, 0);
    cudaStreamWaitEvent(s1, e_fork, 0);

    cvt_hl_kernel<<<(NINNER * NC / 2 + 255) / 256, 256, 0, s1>>>(q_pw,  wq_h,  wq_l,  NINNER * NC / 2);
    cvt_hl_kernel<<<(2 * NINNER * NC / 2 + 255) / 256, 256, 0, s1>>>(kv_pw, wkv_h, wkv_l, 2 * NINNER * NC / 2);
    cvt_hl_kernel<<<(NC * NINNER / 2 + 255) / 256, 256, 0, s1>>>(out_w, wo_h,  wo_l,  NC * NINNER / 2);
    cudaEventRecord(e_cvt, s1);

    dwbn_fused<<<dim3(NB * NC, 2), 256>>>(x, y,
        q_dw_w, q_g, q_b, q_m, q_v,
        kv_dw_w, kv_g, kv_b, kv_m, kv_v);
    cudaEventRecord(e_dw, 0);

    cudaStreamWaitEvent(s1, e_dw, 0);
    mm_gemm2<<<dim3(NP2 / 128, (2 * NINNER) / 128, 2 * NB), 256, GSM2, s1>>>(
        wkv_h, wkv_l, hkv_h, hkv_l, kv_hp, kv_lp, nullptr, nullptr,
        2 * NINNER, NC, NP2);
    cudaEventRecord(e_kv, s1);

    cudaStreamWaitEvent(0, e_cvt, 0);
    mm_gemm2<<<dim3(NP1 / 128, NINNER / 128, 2 * NB), 256, GSM2>>>(
        wq_h, wq_l, hq_h, hq_l, q_hp, q_lp, nullptr, nullptr,
        NINNER, NC, NP1);

    cudaStreamWaitEvent(0, e_kv, 0);
    mm_attn4<<<dim3(2 * NB * 8 / 2, 2), 512, ATT_SM4>>>();

    mm_gemm2<<<dim3(NP1 / 128, NC / 128, 2 * NB), 256, GSM2>>>(
        wo_h, wo_l, ao_h, ao_l, nullptr, nullptr, out, out_b,
        NC, NINNER, NP1);
}

// round 13
// speedup vs baseline: 1.0320x; 1.0200x over previous
#include <cuda_runtime.h>
#include <cuda_bf16.h>
#include <stdint.h>
#include <math.h>

#define NB 8
#define NC 256
#define NP1 1024
#define NP2 256
#define NINNER 512
#define BN_EPS 1e-5f

// ---------------- bf16 hi/lo scratch ----------------
__device__ __nv_bfloat16 g_hq_h [2][NB][NC][NP1],      g_hq_l [2][NB][NC][NP1];
__device__ __nv_bfloat16 g_hkv_h[2][NB][NC][NP2],      g_hkv_l[2][NB][NC][NP2];
__device__ __nv_bfloat16 g_q_h  [2][NB][NINNER][NP1],  g_q_l  [2][NB][NINNER][NP1];
__device__ __nv_bfloat16 g_kv_h [2][NB][2*NINNER][NP2],g_kv_l [2][NB][2*NINNER][NP2];
__device__ __nv_bfloat16 g_ao_h [2][NB][NINNER][NP1],  g_ao_l [2][NB][NINNER][NP1];
__device__ __nv_bfloat16 g_wq_h [NINNER*NC],   g_wq_l [NINNER*NC];
__device__ __nv_bfloat16 g_wkv_h[2*NINNER*NC], g_wkv_l[2*NINNER*NC];
__device__ __nv_bfloat16 g_wo_h [NC*NINNER],   g_wo_l [NC*NINNER];

// ---------------- helpers ----------------
__device__ __forceinline__ uint32_t smem_u32(const void* p){
    uint32_t a;
    asm("{ .reg .u64 t; cvta.to.shared.u64 t, %1; cvt.u32.u64 %0, t; }" : "=r"(a) : "l"(p));
    return a;
}
__device__ __forceinline__ void ldmx4(uint32_t* r, uint32_t a){
    asm volatile("ldmatrix.sync.aligned.m8n8.x4.shared.b16 {%0,%1,%2,%3}, [%4];"
        : "=r"(r[0]),"=r"(r[1]),"=r"(r[2]),"=r"(r[3]) : "r"(a) : "memory");
}
__device__ __forceinline__ void ldmx4t(uint32_t* r, uint32_t a){
    asm volatile("ldmatrix.sync.aligned.m8n8.x4.trans.shared.b16 {%0,%1,%2,%3}, [%4];"
        : "=r"(r[0]),"=r"(r[1]),"=r"(r[2]),"=r"(r[3]) : "r"(a) : "memory");
}
__device__ __forceinline__ void mma16816(float* c, const uint32_t* a, const uint32_t* b){
    asm volatile("mma.sync.aligned.m16n8k16.row.col.f32.bf16.bf16.f32 "
        "{%0,%1,%2,%3}, {%4,%5,%6,%7}, {%8,%9}, {%0,%1,%2,%3};"
        : "+f"(c[0]),"+f"(c[1]),"+f"(c[2]),"+f"(c[3])
        : "r"(a[0]),"r"(a[1]),"r"(a[2]),"r"(a[3]),"r"(b[0]),"r"(b[1]));
}
__device__ __forceinline__ void cpa16(uint32_t s, const void* g){
    asm volatile("cp.async.cg.shared.global [%0], [%1], 16;" :: "r"(s), "l"(g));
}
#define CP_COMMIT() asm volatile("cp.async.commit_group;" ::: "memory")
#define CP_WAIT0()  asm volatile("cp.async.wait_group 0;" ::: "memory")
#define CP_WAIT1()  asm volatile("cp.async.wait_group 1;" ::: "memory")

// hi/lo split with packed converts + bit-shift reconstruction (bit-identical to
// the scalar __float2bfloat16 version: same RN rounding, exact hi as fp32).
__device__ __forceinline__ void put_hl2(__nv_bfloat16* bh, __nv_bfloat16* bl, int idx, float v0, float v1){
    uint32_t hp;
    asm("cvt.rn.bf16x2.f32 %0, %1, %2;" : "=r"(hp) : "f"(v1), "f"(v0));
    float h0 = __uint_as_float(hp << 16);
    float h1 = __uint_as_float(hp & 0xFFFF0000u);
    uint32_t lp;
    float l0 = v0 - h0, l1 = v1 - h1;
    asm("cvt.rn.bf16x2.f32 %0, %1, %2;" : "=r"(lp) : "f"(l1), "f"(l0));
    *(uint32_t*)(bh + idx) = hp;
    *(uint32_t*)(bl + idx) = lp;
}
__device__ __forceinline__ void put_hl(__nv_bfloat16* bh, __nv_bfloat16* bl, int idx, float v){
    __nv_bfloat16 h = __float2bfloat16(v);
    bh[idx] = h;
    float hf = __uint_as_float(((uint32_t)__bfloat16_as_ushort(h)) << 16);
    bl[idx] = __float2bfloat16(v - hf);
}

// ---------------- weight fp32 -> hi/lo ----------------
__global__ void cvt_hl_kernel(const float* __restrict__ src, __nv_bfloat16* __restrict__ h,
                              __nv_bfloat16* __restrict__ l, int n2){
    int i = blockIdx.x * 256 + threadIdx.x;
    if (i < n2) {
        float2 v = *(const float2*)(src + i * 2);
        put_hl2(h, l, i * 2, v.x, v.y);
    }
}

// ---------------- fused depthwise conv (s1 + s2) + BN -> bf16 hi/lo ----------------
__global__ __launch_bounds__(256)
void dwbn_fused(const float* __restrict__ x0, const float* __restrict__ x1,
                const float* __restrict__ qw, const float* __restrict__ qg,
                const float* __restrict__ qb, const float* __restrict__ qm,
                const float* __restrict__ qv,
                const float* __restrict__ kw, const float* __restrict__ kg,
                const float* __restrict__ kb, const float* __restrict__ km,
                const float* __restrict__ kvv)
{
    int inp = blockIdx.y, bc = blockIdx.x, c = bc & 255, b = bc >> 8;
    const float* in = (inp ? x1 : x0) + (size_t)bc * 1024;
    __shared__ float t[34][36];
    int tid = threadIdx.x;

    if (tid < 34) { t[0][tid] = 0.f; t[33][tid] = 0.f; }
    else if (tid < 66) { int r = tid - 33; t[r][0] = 0.f; t[r][33] = 0.f; }

    {
        int r = tid >> 3, q = (tid & 7) * 4;
        float4 v = *(const float4*)(in + r * 32 + q);
        t[r + 1][q + 1] = v.x; t[r + 1][q + 2] = v.y;
        t[r + 1][q + 3] = v.z; t[r + 1][q + 4] = v.w;
    }

    float qwr[9], kwr[9];
#pragma unroll
    for (int i = 0; i < 9; i++) { qwr[i] = qw[c * 9 + i]; kwr[i] = kw[c * 9 + i]; }
    float qs  = qg[c] * rsqrtf(qv[c] + BN_EPS);
    float qsh = qb[c] - qm[c] * qs;
    float ks  = kg[c] * rsqrtf(kvv[c] + BN_EPS);
    float ksh = kb[c] - km[c] * ks;
    __syncthreads();

    {
        int oy = tid >> 3, ox = (tid & 7) * 4;
        float o0 = 0.f, o1 = 0.f, o2 = 0.f, o3 = 0.f;
#pragma unroll
        for (int dy = 0; dy < 3; dy++) {
            float a0 = t[oy + dy][ox + 0], a1 = t[oy + dy][ox + 1], a2 = t[oy + dy][ox + 2];
            float a3 = t[oy + dy][ox + 3], a4 = t[oy + dy][ox + 4], a5 = t[oy + dy][ox + 5];
            float w0 = qwr[dy * 3], w1 = qwr[dy * 3 + 1], w2 = qwr[dy * 3 + 2];
            o0 += a0 * w0 + a1 * w1 + a2 * w2;
            o1 += a1 * w0 + a2 * w1 + a3 * w2;
            o2 += a2 * w0 + a3 * w1 + a4 * w2;
            o3 += a3 * w0 + a4 * w1 + a5 * w2;
        }
        o0 = o0 * qs + qsh; o1 = o1 * qs + qsh;
        o2 = o2 * qs + qsh; o3 = o3 * qs + qsh;
        int idx = oy * 32 + ox;
        put_hl2(&g_hq_h[inp][b][c][0], &g_hq_l[inp][b][c][0], idx, o0, o1);
        put_hl2(&g_hq_h[inp][b][c][0], &g_hq_l[inp][b][c][0], idx + 2, o2, o3);
    }

    {
        int oy = tid >> 4, ox = tid & 15;
        float a = 0.f;
#pragma unroll
        for (int dy = 0; dy < 3; dy++)
#pragma unroll
            for (int dx = 0; dx < 3; dx++)
                a += t[oy * 2 + dy][ox * 2 + dx] * kwr[dy * 3 + dx];
        a = a * ks + ksh;
        put_hl(&g_hkv_h[inp][b][c][0], &g_hkv_l[inp][b][c][0], oy * 16 + ox, a);
    }
}

// ---------------- tensor-core GEMM (R10 config: 2-stage, 2 CTAs/SM) ----------------
#define ALD2 40
#define BLD2 136
#define A_H0 0
#define A_H1 10240
#define A_L0 20480
#define A_L1 30720
#define B_H0 40960
#define B_H1 49664
#define B_L0 58368
#define B_L1 67072
#define GSM2 75776
#define ELD 136
#define ELDF 136

__global__ __launch_bounds__(256, 2)
void mm_gemm2(const __nv_bfloat16* __restrict__ Ah, const __nv_bfloat16* __restrict__ Al,
              const __nv_bfloat16* __restrict__ Bh, const __nv_bfloat16* __restrict__ Bl,
              __nv_bfloat16* __restrict__ Ch, __nv_bfloat16* __restrict__ Cl,
              float* __restrict__ Cf, const float* __restrict__ bias,
              int Mtot, int K, int P)
{
    extern __shared__ char sm[];
    uint32_t sb = smem_u32(sm);
    int tid = threadIdx.x, lane = tid & 31, wid = tid >> 5;
    int wr = wid >> 1, wc = wid & 1;
    int m0 = blockIdx.y * 128, n0 = blockIdx.x * 128;
    size_t zoff = (size_t)blockIdx.z * K * P;
    const __nv_bfloat16* Bhz = Bh + zoff;
    const __nv_bfloat16* Blz = Bl + zoff;

    float acc[2][8][4];
#pragma unroll
    for (int i = 0; i < 2; i++)
#pragma unroll
        for (int j = 0; j < 8; j++)
#pragma unroll
            for (int k = 0; k < 4; k++) acc[i][j][k] = 0.f;

    int niter = K >> 5;

#define LOAD_STAGE(st, k0) do { \
    uint32_t aH = sb + ((st) ? A_H1 : A_H0); \
    uint32_t aL = sb + ((st) ? A_L1 : A_L0); \
    uint32_t bH = sb + ((st) ? B_H1 : B_H0); \
    uint32_t bL = sb + ((st) ? B_L1 : B_L0); \
    _Pragma("unroll") \
    for (int u = 0; u < 2; u++) { \
        int idx = tid + u * 256; \
        int row = idx >> 2, ch = (idx & 3) * 8; \
        size_t go = (size_t)(m0 + row) * K + (k0) + ch; \
        uint32_t so = (uint32_t)(row * ALD2 + ch) * 2; \
        cpa16(aH + so, Ah + go); \
        cpa16(aL + so, Al + go); \
    } \
    _Pragma("unroll") \
    for (int u = 0; u < 2; u++) { \
        int idx = tid + u * 256; \
        int row = idx >> 4, ch = (idx & 15) * 8; \
        size_t go = (size_t)((k0) + row) * P + n0 + ch; \
        uint32_t so = (uint32_t)(row * BLD2 + ch) * 2; \
        cpa16(bH + so, Bhz + go); \
        cpa16(bL + so, Blz + go); \
    } \
} while (0)

    LOAD_STAGE(0, 0);
    CP_COMMIT();

    for (int it = 0; it < niter; it++) {
        if (it + 1 < niter) { LOAD_STAGE((it + 1) & 1, (it + 1) << 5); CP_COMMIT(); CP_WAIT1(); }
        else CP_WAIT0();
        __syncthreads();

        uint32_t aHb = sb + ((it & 1) ? A_H1 : A_H0);
        uint32_t bHb = sb + ((it & 1) ? B_H1 : B_H0);
#pragma unroll
        for (int kk = 0; kk < 2; kk++) {
            uint32_t ah[2][4], al[2][4];
#pragma unroll
            for (int mi = 0; mi < 2; mi++) {
                uint32_t aaddr = aHb + (uint32_t)((wr*32 + mi*16 + (lane & 15)) * ALD2
                                                  + kk*16 + (lane >> 4) * 8) * 2;
                ldmx4(ah[mi], aaddr);
                ldmx4(al[mi], aaddr + 20480u);
            }
#pragma unroll
            for (int ni2 = 0; ni2 < 4; ni2++) {
                uint32_t bh[4], bl[4];
                uint32_t baddr = bHb + (uint32_t)((kk*16 + (lane & 15)) * BLD2
                                                  + wc*64 + ni2*16 + ((lane & 16) >> 1)) * 2;
                ldmx4t(bh, baddr);
                ldmx4t(bl, baddr + 17408u);
#pragma unroll
                for (int mi = 0; mi < 2; mi++) {
                    mma16816(acc[mi][ni2*2],   ah[mi], &bh[0]);
                    mma16816(acc[mi][ni2*2],   ah[mi], &bl[0]);
                    mma16816(acc[mi][ni2*2],   al[mi], &bh[0]);
                    mma16816(acc[mi][ni2*2+1], ah[mi], &bh[2]);
                    mma16816(acc[mi][ni2*2+1], ah[mi], &bl[2]);
                    mma16816(acc[mi][ni2*2+1], al[mi], &bh[2]);
                }
            }
        }
        __syncthreads();
    }

    if (Cf) {
        float* Ef = (float*)sm;
        float* Cp = Cf + (size_t)blockIdx.z * Mtot * P;
#pragma unroll
        for (int mi = 0; mi < 2; mi++) {
            int row = wr*32 + mi*16 + (lane >> 2);
            float b0 = bias ? bias[m0 + row] : 0.f;
            float b1 = bias ? bias[m0 + row + 8] : 0.f;
#pragma unroll
            for (int ni = 0; ni < 8; ni++) {
                int col = wc*64 + ni*8 + (lane & 3) * 2;
                *(float2*)&Ef[row * ELDF + col] =
                    make_float2(acc[mi][ni][0] + b0, acc[mi][ni][1] + b0);
                *(float2*)&Ef[(row + 8) * ELDF + col] =
                    make_float2(acc[mi][ni][2] + b1, acc[mi][ni][3] + b1);
            }
        }
        __syncthreads();
#pragma unroll
        for (int u = 0; u < 16; u++) {
            int linear = tid + u * 256;
            int row = linear >> 5, c4 = (linear & 31) * 4;
            *(float4*)&Cp[(size_t)(m0 + row) * P + n0 + c4] =
                *(const float4*)&Ef[row * ELDF + c4];
        }
    } else {
        __nv_bfloat16* Eh = (__nv_bfloat16*)sm;
        __nv_bfloat16* El = (__nv_bfloat16*)(sm + 128 * ELD * 2);
#pragma unroll
        for (int mi = 0; mi < 2; mi++) {
            int row = wr*32 + mi*16 + (lane >> 2);
#pragma unroll
            for (int ni = 0; ni < 8; ni++) {
                int col = wc*64 + ni*8 + (lane & 3) * 2;
                put_hl2(Eh, El, row * ELD + col, acc[mi][ni][0], acc[mi][ni][1]);
                put_hl2(Eh, El, (row + 8) * ELD + col, acc[mi][ni][2], acc[mi][ni][3]);
            }
        }
        __syncthreads();
        __nv_bfloat16* Chz = Ch + (size_t)blockIdx.z * Mtot * P;
        __nv_bfloat16* Clz = Cl + (size_t)blockIdx.z * Mtot * P;
#pragma unroll
        for (int u = 0; u < 8; u++) {
            int linear = tid + u * 256;
            int row = linear >> 4, c8 = (linear & 15) * 8;
            size_t go = (size_t)(m0 + row) * P + n0 + c8;
            *(uint4*)&Chz[go] = *(const uint4*)&Eh[row * ELD + c8];
            *(uint4*)&Clz[go] = *(const uint4*)&El[row * ELD + c8];
        }
    }
}

// ---------------- fused attention v5 (R10 structure) ----------------
#define QLD4 72
#define KLD4 264
#define PLD4 264
#define OLD4 65
#define AQH4 0
#define AQL4 9216
#define AKH4 18432
#define AKL4 52224
#define AVH4 86016
#define AVL4 119808
#define APH4 153600
#define APL4 187392
#define AREDM 221184
#define AREDS 222208
#define ATT_SM4 223232

__global__ __launch_bounds__(512)
void mm_attn4()
{
    extern __shared__ char sm[];
    uint32_t sb = smem_u32(sm);
    float* red_m = (float*)(sm + AREDM);
    float* red_s = (float*)(sm + AREDS);
    float* O   = (float*)(sm + APH4);
    __nv_bfloat16* Ph = (__nv_bfloat16*)(sm + APH4);
    __nv_bfloat16* Pl = (__nv_bfloat16*)(sm + APL4);

    int tid = threadIdx.x, lane = tid & 31, wid = tid >> 5;
    int bh = blockIdx.x, dir = blockIdx.y;
    int b = bh >> 3, h = bh & 7;
    int qin = dir, kin = dir ^ 1;
    int wr = wid >> 2, wc = wid & 3;

    const __nv_bfloat16* qh = &g_q_h[qin][b][0][0];
    const __nv_bfloat16* ql = &g_q_l[qin][b][0][0];
    const __nv_bfloat16* kh = &g_kv_h[kin][b][0][0];
    const __nv_bfloat16* kl = &g_kv_l[kin][b][0][0];

    int qhalf = tid >> 8, qt = tid & 255;
    int qd = qt >> 2, qch = (qt & 3) * 16;
    const __nv_bfloat16* qsrc = (qhalf ? ql : qh) + (size_t)(h * 64 + qd) * NP1 + qch;
    uint32_t qdst = sb + (qhalf ? AQL4 : AQH4) + (uint32_t)(qd * QLD4 + qch) * 2;

#pragma unroll
    for (int u = 0; u < 4; u++) {
        int idx = tid + u * 512;
        int d = idx >> 5, ch = (idx & 31) * 8;
        size_t gk = (size_t)(h * 64 + d) * NP2 + ch;
        size_t gv = (size_t)(NINNER + h * 64 + d) * NP2 + ch;
        uint32_t so = (uint32_t)(d * KLD4 + ch) * 2;
        cpa16(sb + AKH4 + so, kh + gk);
        cpa16(sb + AKL4 + so, kl + gk);
        cpa16(sb + AVH4 + so, kh + gv);
        cpa16(sb + AVL4 + so, kl + gv);
    }
    cpa16(qdst, qsrc);
    cpa16(qdst + 16, qsrc + 8);
    CP_COMMIT();

    int rA = wr * 16 + (lane >> 2);
    int rB = rA + 8;

    for (int it = 0; it < 16; it++) {
        CP_WAIT0();
        __syncthreads();
        int i0 = it * 64;

        float acc[8][4];
#pragma unroll
        for (int i = 0; i < 8; i++)
#pragma unroll
            for (int k = 0; k < 4; k++) acc[i][k] = 0.f;

#pragma unroll
        for (int kk = 0; kk < 4; kk++) {
            uint32_t ah[4], al[4];
            uint32_t krow = (uint32_t)(kk*16 + (lane & 7) + ((lane >> 1) & 8));
            uint32_t acol = (uint32_t)(wr*16 + (lane & 8));
            uint32_t aaddr = sb + AQH4 + (krow * QLD4 + acol) * 2;
            ldmx4t(ah, aaddr);
            ldmx4t(al, aaddr + (AQL4 - AQH4));
#pragma unroll
            for (int ni2 = 0; ni2 < 4; ni2++) {
                uint32_t bhf[4], blf[4];
                uint32_t baddr = sb + AKH4 + (uint32_t)((kk*16 + (lane & 15)) * KLD4
                                                        + wc*64 + ni2*16 + ((lane & 16) >> 1)) * 2;
                ldmx4t(bhf, baddr);
                ldmx4t(blf, baddr + (AKL4 - AKH4));
                mma16816(acc[ni2*2],   ah, &bhf[0]);
                mma16816(acc[ni2*2],   ah, &blf[0]);
                mma16816(acc[ni2*2],   al, &bhf[0]);
                mma16816(acc[ni2*2+1], ah, &bhf[2]);
                mma16816(acc[ni2*2+1], ah, &blf[2]);
                mma16816(acc[ni2*2+1], al, &bhf[2]);
            }
        }
        __syncthreads();

        if (it + 1 < 16) {
            const __nv_bfloat16* nq = qsrc + (it + 1) * 64;
            cpa16(qdst, nq);
            cpa16(qdst + 16, nq + 8);
            CP_COMMIT();
        }

#pragma unroll
        for (int ni = 0; ni < 8; ni++)
#pragma unroll
            for (int k = 0; k < 4; k++) acc[ni][k] *= 0.125f;

        float mA = -1e30f, mB = -1e30f;
#pragma unroll
        for (int ni = 0; ni < 8; ni++) {
            mA = fmaxf(mA, fmaxf(acc[ni][0], acc[ni][1]));
            mB = fmaxf(mB, fmaxf(acc[ni][2], acc[ni][3]));
        }
        mA = fmaxf(mA, __shfl_xor_sync(0xffffffffu, mA, 1));
        mA = fmaxf(mA, __shfl_xor_sync(0xffffffffu, mA, 2));
        mB = fmaxf(mB, __shfl_xor_sync(0xffffffffu, mB, 1));
        mB = fmaxf(mB, __shfl_xor_sync(0xffffffffu, mB, 2));
        if ((lane & 3) == 0) { red_m[rA * 4 + wc] = mA; red_m[rB * 4 + wc] = mB; }
        __syncthreads();
        mA = fmaxf(fmaxf(red_m[rA*4], red_m[rA*4+1]), fmaxf(red_m[rA*4+2], red_m[rA*4+3]));
        mB = fmaxf(fmaxf(red_m[rB*4], red_m[rB*4+1]), fmaxf(red_m[rB*4+2], red_m[rB*4+3]));

        float sA = 0.f, sB = 0.f;
#pragma unroll
        for (int ni = 0; ni < 8; ni++) {
            acc[ni][0] = __expf(acc[ni][0] - mA);
            acc[ni][1] = __expf(acc[ni][1] - mA);
            acc[ni][2] = __expf(acc[ni][2] - mB);
            acc[ni][3] = __expf(acc[ni][3] - mB);
            sA += acc[ni][0] + acc[ni][1];
            sB += acc[ni][2] + acc[ni][3];
        }
        sA += __shfl_xor_sync(0xffffffffu, sA, 1);
        sA += __shfl_xor_sync(0xffffffffu, sA, 2);
        sB += __shfl_xor_sync(0xffffffffu, sB, 1);
        sB += __shfl_xor_sync(0xffffffffu, sB, 2);
        if ((lane & 3) == 0) { red_s[rA * 4 + wc] = sA; red_s[rB * 4 + wc] = sB; }
        __syncthreads();
        float invA = 1.f / (red_s[rA*4] + red_s[rA*4+1] + red_s[rA*4+2] + red_s[rA*4+3]);
        float invB = 1.f / (red_s[rB*4] + red_s[rB*4+1] + red_s[rB*4+2] + red_s[rB*4+3]);

#pragma unroll
        for (int ni = 0; ni < 8; ni++) {
            int c = wc*64 + ni*8 + (lane & 3) * 2;
            put_hl2(Ph, Pl, rA * PLD4 + c, acc[ni][0] * invA, acc[ni][1] * invA);
            put_hl2(Ph, Pl, rB * PLD4 + c, acc[ni][2] * invB, acc[ni][3] * invB);
        }
        __syncthreads();

        float acc2[2][4];
#pragma unroll
        for (int i = 0; i < 2; i++)
#pragma unroll
            for (int k = 0; k < 4; k++) acc2[i][k] = 0.f;

#pragma unroll 4
        for (int kk = 0; kk < 16; kk++) {
            uint32_t ah[4], al[4];
            uint32_t aaddr = sb + APH4 + (uint32_t)((wr*16 + (lane & 15)) * PLD4
                                                    + kk*16 + (lane >> 4) * 8) * 2;
            ldmx4(ah, aaddr);
            ldmx4(al, aaddr + (APL4 - APH4));
            uint32_t bhf[4], blf[4];
            uint32_t baddr = sb + AVH4 + (uint32_t)((wc*16 + ((lane >> 4) & 1) * 8 + (lane & 7)) * KLD4
                                                    + kk*16 + ((lane >> 3) & 1) * 8) * 2;
            ldmx4(bhf, baddr);
            ldmx4(blf, baddr + (AVL4 - AVH4));
            mma16816(acc2[0], ah, &bhf[0]);
            mma16816(acc2[0], ah, &blf[0]);
            mma16816(acc2[0], al, &bhf[0]);
            mma16816(acc2[1], ah, &bhf[2]);
            mma16816(acc2[1], ah, &blf[2]);
            mma16816(acc2[1], al, &bhf[2]);
        }
        __syncthreads();

#pragma unroll
        for (int ni = 0; ni < 2; ni++) {
            int c = wc*16 + ni*8 + (lane & 3) * 2;
            O[rA * OLD4 + c]     = acc2[ni][0];
            O[rA * OLD4 + c + 1] = acc2[ni][1];
            O[rB * OLD4 + c]     = acc2[ni][2];
            O[rB * OLD4 + c + 1] = acc2[ni][3];
        }
        __syncthreads();
        {
            int d = tid >> 3, ip = (tid & 7) * 8;
            __nv_bfloat16* aoh = &g_ao_h[qin][b][h * 64 + d][i0 + ip];
            __nv_bfloat16* aol = &g_ao_l[qin][b][h * 64 + d][i0 + ip];
#pragma unroll
            for (int u = 0; u < 8; u += 2) {
                float v0 = O[(ip + u) * OLD4 + d];
                float v1 = O[(ip + u + 1) * OLD4 + d];
                put_hl2(aoh, aol, u, v0, v1);
            }
        }
    }
}

// ---------------- launch ----------------
extern "C" void kernel_launch(void* const* d_in, const int* in_sizes, int n_in,
                              void* d_out, int out_size)
{
    const float* x      = (const float*)d_in[0];
    const float* y      = (const float*)d_in[1];
    const float* q_dw_w = (const float*)d_in[2];
    const float* q_g    = (const float*)d_in[3];
    const float* q_b    = (const float*)d_in[4];
    const float* q_m    = (const float*)d_in[5];
    const float* q_v    = (const float*)d_in[6];
    const float* q_pw   = (const float*)d_in[7];
    const float* kv_dw_w= (const float*)d_in[8];
    const float* kv_g   = (const float*)d_in[9];
    const float* kv_b   = (const float*)d_in[10];
    const float* kv_m   = (const float*)d_in[11];
    const float* kv_v   = (const float*)d_in[12];
    const float* kv_pw  = (const float*)d_in[13];
    const float* out_w  = (const float*)d_in[14];
    const float* out_b  = (const float*)d_in[15];
    float* out = (float*)d_out;

    __nv_bfloat16 *wq_h, *wq_l, *wkv_h, *wkv_l, *wo_h, *wo_l;
    __nv_bfloat16 *hq_h, *hq_l, *hkv_h, *hkv_l, *q_hp, *q_lp, *kv_hp, *kv_lp, *ao_h, *ao_l;
    cudaGetSymbolAddress((void**)&wq_h,  g_wq_h);  cudaGetSymbolAddress((void**)&wq_l,  g_wq_l);
    cudaGetSymbolAddress((void**)&wkv_h, g_wkv_h); cudaGetSymbolAddress((void**)&wkv_l, g_wkv_l);
    cudaGetSymbolAddress((void**)&wo_h,  g_wo_h);  cudaGetSymbolAddress((void**)&wo_l,  g_wo_l);
    cudaGetSymbolAddress((void**)&hq_h,  g_hq_h);  cudaGetSymbolAddress((void**)&hq_l,  g_hq_l);
    cudaGetSymbolAddress((void**)&hkv_h, g_hkv_h); cudaGetSymbolAddress((void**)&hkv_l, g_hkv_l);
    cudaGetSymbolAddress((void**)&q_hp,  g_q_h);   cudaGetSymbolAddress((void**)&q_lp,  g_q_l);
    cudaGetSymbolAddress((void**)&kv_hp, g_kv_h);  cudaGetSymbolAddress((void**)&kv_lp, g_kv_l);
    cudaGetSymbolAddress((void**)&ao_h,  g_ao_h);  cudaGetSymbolAddress((void**)&ao_l,  g_ao_l);

    static cudaStream_t s1 = nullptr;
    static cudaEvent_t e_fork, e_cvt, e_dw, e_kv;
    if (!s1) {
        cudaStreamCreateWithFlags(&s1, cudaStreamNonBlocking);
        cudaEventCreateWithFlags(&e_fork, cudaEventDisableTiming);
        cudaEventCreateWithFlags(&e_cvt,  cudaEventDisableTiming);
        cudaEventCreateWithFlags(&e_dw,   cudaEventDisableTiming);
        cudaEventCreateWithFlags(&e_kv,   cudaEventDisableTiming);
        cudaFuncSetAttribute(mm_attn4, cudaFuncAttributeMaxDynamicSharedMemorySize, ATT_SM4);
        cudaFuncSetAttribute(mm_gemm2, cudaFuncAttributeMaxDynamicSharedMemorySize, GSM2);
    }

    cudaEventRecord(e_fork, 0);
    cudaStreamWaitEvent(s1, e_fork, 0);

    cvt_hl_kernel<<<(NINNER * NC / 2 + 255) / 256, 256, 0, s1>>>(q_pw,  wq_h,  wq_l,  NINNER * NC / 2);
    cvt_hl_kernel<<<(2 * NINNER * NC / 2 + 255) / 256, 256, 0, s1>>>(kv_pw, wkv_h, wkv_l, 2 * NINNER * NC / 2);
    cvt_hl_kernel<<<(NC * NINNER / 2 + 255) / 256, 256, 0, s1>>>(out_w, wo_h,  wo_l,  NC * NINNER / 2);
    cudaEventRecord(e_cvt, s1);

    dwbn_fused<<<dim3(NB * NC, 2), 256>>>(x, y,
        q_dw_w, q_g, q_b, q_m, q_v,
        kv_dw_w, kv_g, kv_b, kv_m, kv_v);
    cudaEventRecord(e_dw, 0);

    cudaStreamWaitEvent(s1, e_dw, 0);
    mm_gemm2<<<dim3(NP2 / 128, (2 * NINNER) / 128, 2 * NB), 256, GSM2, s1>>>(
        wkv_h, wkv_l, hkv_h, hkv_l, kv_hp, kv_lp, nullptr, nullptr,
        2 * NINNER, NC, NP2);
    cudaEventRecord(e_kv, s1);

    cudaStreamWaitEvent(0, e_cvt, 0);
    mm_gemm2<<<dim3(NP1 / 128, NINNER / 128, 2 * NB), 256, GSM2>>>(
        wq_h, wq_l, hq_h, hq_l, q_hp, q_lp, nullptr, nullptr,
        NINNER, NC, NP1);

    cudaStreamWaitEvent(0, e_kv, 0);
    mm_attn4<<<dim3(2 * NB * 8 / 2, 2), 512, ATT_SM4>>>();

    mm_gemm2<<<dim3(NP1 / 128, NC / 128, 2 * NB), 256, GSM2>>>(
        wo_h, wo_l, ao_h, ao_l, nullptr, nullptr, out, out_b,
        NC, NINNER, NP1);
}

// round 14
// speedup vs baseline: 1.0547x; 1.0220x over previous
#include <cuda_runtime.h>
#include <cuda_bf16.h>
#include <stdint.h>
#include <math.h>

#define NB 8
#define NC 256
#define NP1 1024
#define NP2 256
#define NINNER 512
#define BN_EPS 1e-5f

// ---------------- bf16 hi/lo scratch ----------------
__device__ __nv_bfloat16 g_hq_h [2][NB][NC][NP1],      g_hq_l [2][NB][NC][NP1];
__device__ __nv_bfloat16 g_hkv_h[2][NB][NC][NP2],      g_hkv_l[2][NB][NC][NP2];
__device__ __nv_bfloat16 g_q_h  [2][NB][NINNER][NP1],  g_q_l  [2][NB][NINNER][NP1];
__device__ __nv_bfloat16 g_kv_h [2][NB][2*NINNER][NP2],g_kv_l [2][NB][2*NINNER][NP2];
__device__ __nv_bfloat16 g_ao_h [2][NB][NINNER][NP1],  g_ao_l [2][NB][NINNER][NP1];
__device__ __nv_bfloat16 g_wq_h [NINNER*NC],   g_wq_l [NINNER*NC];
__device__ __nv_bfloat16 g_wkv_h[2*NINNER*NC], g_wkv_l[2*NINNER*NC];
__device__ __nv_bfloat16 g_wo_h [NC*NINNER],   g_wo_l [NC*NINNER];

// ---------------- helpers ----------------
__device__ __forceinline__ uint32_t smem_u32(const void* p){
    uint32_t a;
    asm("{ .reg .u64 t; cvta.to.shared.u64 t, %1; cvt.u32.u64 %0, t; }" : "=r"(a) : "l"(p));
    return a;
}
__device__ __forceinline__ void ldmx4(uint32_t* r, uint32_t a){
    asm volatile("ldmatrix.sync.aligned.m8n8.x4.shared.b16 {%0,%1,%2,%3}, [%4];"
        : "=r"(r[0]),"=r"(r[1]),"=r"(r[2]),"=r"(r[3]) : "r"(a) : "memory");
}
__device__ __forceinline__ void ldmx4t(uint32_t* r, uint32_t a){
    asm volatile("ldmatrix.sync.aligned.m8n8.x4.trans.shared.b16 {%0,%1,%2,%3}, [%4];"
        : "=r"(r[0]),"=r"(r[1]),"=r"(r[2]),"=r"(r[3]) : "r"(a) : "memory");
}
__device__ __forceinline__ void mma16816(float* c, const uint32_t* a, const uint32_t* b){
    asm volatile("mma.sync.aligned.m16n8k16.row.col.f32.bf16.bf16.f32 "
        "{%0,%1,%2,%3}, {%4,%5,%6,%7}, {%8,%9}, {%0,%1,%2,%3};"
        : "+f"(c[0]),"+f"(c[1]),"+f"(c[2]),"+f"(c[3])
        : "r"(a[0]),"r"(a[1]),"r"(a[2]),"r"(a[3]),"r"(b[0]),"r"(b[1]));
}
__device__ __forceinline__ void cpa16(uint32_t s, const void* g){
    asm volatile("cp.async.cg.shared.global [%0], [%1], 16;" :: "r"(s), "l"(g));
}
#define CP_COMMIT() asm volatile("cp.async.commit_group;" ::: "memory")
#define CP_WAIT0()  asm volatile("cp.async.wait_group 0;" ::: "memory")
#define CP_WAIT1()  asm volatile("cp.async.wait_group 1;" ::: "memory")

// hi/lo split, packed converts + bit reconstruction (bit-identical to scalar path)
__device__ __forceinline__ void put_hl2(__nv_bfloat16* bh, __nv_bfloat16* bl, int idx, float v0, float v1){
    uint32_t hp;
    asm("cvt.rn.bf16x2.f32 %0, %1, %2;" : "=r"(hp) : "f"(v1), "f"(v0));
    float h0 = __uint_as_float(hp << 16);
    float h1 = __uint_as_float(hp & 0xFFFF0000u);
    uint32_t lp;
    float l0 = v0 - h0, l1 = v1 - h1;
    asm("cvt.rn.bf16x2.f32 %0, %1, %2;" : "=r"(lp) : "f"(l1), "f"(l0));
    *(uint32_t*)(bh + idx) = hp;
    *(uint32_t*)(bl + idx) = lp;
}
__device__ __forceinline__ void put_hl4(__nv_bfloat16* bh, __nv_bfloat16* bl, int idx,
                                        float v0, float v1, float v2, float v3){
    uint32_t hp0, hp1, lp0, lp1;
    asm("cvt.rn.bf16x2.f32 %0, %1, %2;" : "=r"(hp0) : "f"(v1), "f"(v0));
    asm("cvt.rn.bf16x2.f32 %0, %1, %2;" : "=r"(hp1) : "f"(v3), "f"(v2));
    float h0 = __uint_as_float(hp0 << 16), h1 = __uint_as_float(hp0 & 0xFFFF0000u);
    float h2 = __uint_as_float(hp1 << 16), h3 = __uint_as_float(hp1 & 0xFFFF0000u);
    asm("cvt.rn.bf16x2.f32 %0, %1, %2;" : "=r"(lp0) : "f"(v1 - h1), "f"(v0 - h0));
    asm("cvt.rn.bf16x2.f32 %0, %1, %2;" : "=r"(lp1) : "f"(v3 - h3), "f"(v2 - h2));
    *(uint2*)(bh + idx) = make_uint2(hp0, hp1);
    *(uint2*)(bl + idx) = make_uint2(lp0, lp1);
}
__device__ __forceinline__ void put_hl(__nv_bfloat16* bh, __nv_bfloat16* bl, int idx, float v){
    __nv_bfloat16 h = __float2bfloat16(v);
    bh[idx] = h;
    float hf = __uint_as_float(((uint32_t)__bfloat16_as_ushort(h)) << 16);
    bl[idx] = __float2bfloat16(v - hf);
}

// ---------------- weight fp32 -> hi/lo ----------------
__global__ void cvt_hl_kernel(const float* __restrict__ src, __nv_bfloat16* __restrict__ h,
                              __nv_bfloat16* __restrict__ l, int n2){
    int i = blockIdx.x * 256 + threadIdx.x;
    if (i < n2) {
        float2 v = *(const float2*)(src + i * 2);
        put_hl2(h, l, i * 2, v.x, v.y);
    }
}

// ---------------- fused depthwise conv (s1 + s2) + BN, per-input ----------------
__global__ __launch_bounds__(256)
void dwbn_fused(const float* __restrict__ x0, const float* __restrict__ x1,
                const float* __restrict__ qw, const float* __restrict__ qg,
                const float* __restrict__ qb, const float* __restrict__ qm,
                const float* __restrict__ qv,
                const float* __restrict__ kw, const float* __restrict__ kg,
                const float* __restrict__ kb, const float* __restrict__ km,
                const float* __restrict__ kvv, int inp)
{
    int bc = blockIdx.x, c = bc & 255, b = bc >> 8;
    const float* in = (inp ? x1 : x0) + (size_t)bc * 1024;
    __shared__ float t[34][36];
    int tid = threadIdx.x;

    if (tid < 34) { t[0][tid] = 0.f; t[33][tid] = 0.f; }
    else if (tid < 66) { int r = tid - 33; t[r][0] = 0.f; t[r][33] = 0.f; }

    {
        int r = tid >> 3, q = (tid & 7) * 4;
        float4 v = *(const float4*)(in + r * 32 + q);
        t[r + 1][q + 1] = v.x; t[r + 1][q + 2] = v.y;
        t[r + 1][q + 3] = v.z; t[r + 1][q + 4] = v.w;
    }

    float qwr[9], kwr[9];
#pragma unroll
    for (int i = 0; i < 9; i++) { qwr[i] = qw[c * 9 + i]; kwr[i] = kw[c * 9 + i]; }
    float qs  = qg[c] * rsqrtf(qv[c] + BN_EPS);
    float qsh = qb[c] - qm[c] * qs;
    float ks  = kg[c] * rsqrtf(kvv[c] + BN_EPS);
    float ksh = kb[c] - km[c] * ks;
    __syncthreads();

    {
        int oy = tid >> 3, ox = (tid & 7) * 4;
        float o0 = 0.f, o1 = 0.f, o2 = 0.f, o3 = 0.f;
#pragma unroll
        for (int dy = 0; dy < 3; dy++) {
            float a0 = t[oy + dy][ox + 0], a1 = t[oy + dy][ox + 1], a2 = t[oy + dy][ox + 2];
            float a3 = t[oy + dy][ox + 3], a4 = t[oy + dy][ox + 4], a5 = t[oy + dy][ox + 5];
            float w0 = qwr[dy * 3], w1 = qwr[dy * 3 + 1], w2 = qwr[dy * 3 + 2];
            o0 += a0 * w0 + a1 * w1 + a2 * w2;
            o1 += a1 * w0 + a2 * w1 + a3 * w2;
            o2 += a2 * w0 + a3 * w1 + a4 * w2;
            o3 += a3 * w0 + a4 * w1 + a5 * w2;
        }
        o0 = o0 * qs + qsh; o1 = o1 * qs + qsh;
        o2 = o2 * qs + qsh; o3 = o3 * qs + qsh;
        put_hl4(&g_hq_h[inp][b][c][0], &g_hq_l[inp][b][c][0], oy * 32 + ox, o0, o1, o2, o3);
    }

    {
        int oy = tid >> 4, ox = tid & 15;
        float a = 0.f;
#pragma unroll
        for (int dy = 0; dy < 3; dy++)
#pragma unroll
            for (int dx = 0; dx < 3; dx++)
                a += t[oy * 2 + dy][ox * 2 + dx] * kwr[dy * 3 + dx];
        a = a * ks + ksh;
        put_hl(&g_hkv_h[inp][b][c][0], &g_hkv_l[inp][b][c][0], oy * 16 + ox, a);
    }
}

// ---------------- tensor-core GEMM (2-stage, 2 CTAs/SM) ----------------
#define ALD2 40
#define BLD2 136
#define A_H0 0
#define A_H1 10240
#define A_L0 20480
#define A_L1 30720
#define B_H0 40960
#define B_H1 49664
#define B_L0 58368
#define B_L1 67072
#define GSM2 75776
#define ELD 136
#define ELDF 136

__global__ __launch_bounds__(256, 2)
void mm_gemm2(const __nv_bfloat16* __restrict__ Ah, const __nv_bfloat16* __restrict__ Al,
              const __nv_bfloat16* __restrict__ Bh, const __nv_bfloat16* __restrict__ Bl,
              __nv_bfloat16* __restrict__ Ch, __nv_bfloat16* __restrict__ Cl,
              float* __restrict__ Cf, const float* __restrict__ bias,
              int Mtot, int K, int P)
{
    extern __shared__ char sm[];
    uint32_t sb = smem_u32(sm);
    int tid = threadIdx.x, lane = tid & 31, wid = tid >> 5;
    int wr = wid >> 1, wc = wid & 1;
    int m0 = blockIdx.y * 128, n0 = blockIdx.x * 128;
    size_t zoff = (size_t)blockIdx.z * K * P;
    const __nv_bfloat16* Bhz = Bh + zoff;
    const __nv_bfloat16* Blz = Bl + zoff;

    float acc[2][8][4];
#pragma unroll
    for (int i = 0; i < 2; i++)
#pragma unroll
        for (int j = 0; j < 8; j++)
#pragma unroll
            for (int k = 0; k < 4; k++) acc[i][j][k] = 0.f;

    int niter = K >> 5;

#define LOAD_STAGE(st, k0) do { \
    uint32_t aH = sb + ((st) ? A_H1 : A_H0); \
    uint32_t aL = sb + ((st) ? A_L1 : A_L0); \
    uint32_t bH = sb + ((st) ? B_H1 : B_H0); \
    uint32_t bL = sb + ((st) ? B_L1 : B_L0); \
    _Pragma("unroll") \
    for (int u = 0; u < 2; u++) { \
        int idx = tid + u * 256; \
        int row = idx >> 2, ch = (idx & 3) * 8; \
        size_t go = (size_t)(m0 + row) * K + (k0) + ch; \
        uint32_t so = (uint32_t)(row * ALD2 + ch) * 2; \
        cpa16(aH + so, Ah + go); \
        cpa16(aL + so, Al + go); \
    } \
    _Pragma("unroll") \
    for (int u = 0; u < 2; u++) { \
        int idx = tid + u * 256; \
        int row = idx >> 4, ch = (idx & 15) * 8; \
        size_t go = (size_t)((k0) + row) * P + n0 + ch; \
        uint32_t so = (uint32_t)(row * BLD2 + ch) * 2; \
        cpa16(bH + so, Bhz + go); \
        cpa16(bL + so, Blz + go); \
    } \
} while (0)

    LOAD_STAGE(0, 0);
    CP_COMMIT();

    for (int it = 0; it < niter; it++) {
        if (it + 1 < niter) { LOAD_STAGE((it + 1) & 1, (it + 1) << 5); CP_COMMIT(); CP_WAIT1(); }
        else CP_WAIT0();
        __syncthreads();

        uint32_t aHb = sb + ((it & 1) ? A_H1 : A_H0);
        uint32_t bHb = sb + ((it & 1) ? B_H1 : B_H0);
#pragma unroll
        for (int kk = 0; kk < 2; kk++) {
            uint32_t ah[2][4], al[2][4];
#pragma unroll
            for (int mi = 0; mi < 2; mi++) {
                uint32_t aaddr = aHb + (uint32_t)((wr*32 + mi*16 + (lane & 15)) * ALD2
                                                  + kk*16 + (lane >> 4) * 8) * 2;
                ldmx4(ah[mi], aaddr);
                ldmx4(al[mi], aaddr + 20480u);
            }
#pragma unroll
            for (int ni2 = 0; ni2 < 4; ni2++) {
                uint32_t bh[4], bl[4];
                uint32_t baddr = bHb + (uint32_t)((kk*16 + (lane & 15)) * BLD2
                                                  + wc*64 + ni2*16 + ((lane & 16) >> 1)) * 2;
                ldmx4t(bh, baddr);
                ldmx4t(bl, baddr + 17408u);
#pragma unroll
                for (int mi = 0; mi < 2; mi++) {
                    mma16816(acc[mi][ni2*2],   ah[mi], &bh[0]);
                    mma16816(acc[mi][ni2*2],   ah[mi], &bl[0]);
                    mma16816(acc[mi][ni2*2],   al[mi], &bh[0]);
                    mma16816(acc[mi][ni2*2+1], ah[mi], &bh[2]);
                    mma16816(acc[mi][ni2*2+1], ah[mi], &bl[2]);
                    mma16816(acc[mi][ni2*2+1], al[mi], &bh[2]);
                }
            }
        }
        __syncthreads();
    }

    if (Cf) {
        float* Ef = (float*)sm;
        float* Cp = Cf + (size_t)blockIdx.z * Mtot * P;
#pragma unroll
        for (int mi = 0; mi < 2; mi++) {
            int row = wr*32 + mi*16 + (lane >> 2);
            float b0 = bias ? bias[m0 + row] : 0.f;
            float b1 = bias ? bias[m0 + row + 8] : 0.f;
#pragma unroll
            for (int ni = 0; ni < 8; ni++) {
                int col = wc*64 + ni*8 + (lane & 3) * 2;
                *(float2*)&Ef[row * ELDF + col] =
                    make_float2(acc[mi][ni][0] + b0, acc[mi][ni][1] + b0);
                *(float2*)&Ef[(row + 8) * ELDF + col] =
                    make_float2(acc[mi][ni][2] + b1, acc[mi][ni][3] + b1);
            }
        }
        __syncthreads();
#pragma unroll
        for (int u = 0; u < 16; u++) {
            int linear = tid + u * 256;
            int row = linear >> 5, c4 = (linear & 31) * 4;
            *(float4*)&Cp[(size_t)(m0 + row) * P + n0 + c4] =
                *(const float4*)&Ef[row * ELDF + c4];
        }
    } else {
        __nv_bfloat16* Eh = (__nv_bfloat16*)sm;
        __nv_bfloat16* El = (__nv_bfloat16*)(sm + 128 * ELD * 2);
#pragma unroll
        for (int mi = 0; mi < 2; mi++) {
            int row = wr*32 + mi*16 + (lane >> 2);
#pragma unroll
            for (int ni = 0; ni < 8; ni++) {
                int col = wc*64 + ni*8 + (lane & 3) * 2;
                put_hl2(Eh, El, row * ELD + col, acc[mi][ni][0], acc[mi][ni][1]);
                put_hl2(Eh, El, (row + 8) * ELD + col, acc[mi][ni][2], acc[mi][ni][3]);
            }
        }
        __syncthreads();
        __nv_bfloat16* Chz = Ch + (size_t)blockIdx.z * Mtot * P;
        __nv_bfloat16* Clz = Cl + (size_t)blockIdx.z * Mtot * P;
#pragma unroll
        for (int u = 0; u < 8; u++) {
            int linear = tid + u * 256;
            int row = linear >> 4, c8 = (linear & 15) * 8;
            size_t go = (size_t)(m0 + row) * P + n0 + c8;
            *(uint4*)&Chz[go] = *(const uint4*)&Eh[row * ELD + c8];
            *(uint4*)&Clz[go] = *(const uint4*)&El[row * ELD + c8];
        }
    }
}

// ---------------- fused attention v6: per-dir launch, deferred normalize ----------------
#define QLD4 72
#define KLD4 264
#define PLD4 264
#define OLD4 65
#define AQH4 0
#define AQL4 9216
#define AKH4 18432
#define AKL4 52224
#define AVH4 86016
#define AVL4 119808
#define APH4 153600
#define APL4 187392
#define AREDM 221184
#define AREDS 222208
#define ATT_SM4 223232

__global__ __launch_bounds__(512)
void mm_attn4(int dir)
{
    extern __shared__ char sm[];
    uint32_t sb = smem_u32(sm);
    float* red_m = (float*)(sm + AREDM);
    float* red_s = (float*)(sm + AREDS);
    float* O   = (float*)(sm + APH4);
    __nv_bfloat16* Ph = (__nv_bfloat16*)(sm + APH4);
    __nv_bfloat16* Pl = (__nv_bfloat16*)(sm + APL4);

    int tid = threadIdx.x, lane = tid & 31, wid = tid >> 5;
    int bh = blockIdx.x;
    int b = bh >> 3, h = bh & 7;
    int qin = dir, kin = dir ^ 1;
    int wr = wid >> 2, wc = wid & 3;

    const __nv_bfloat16* qh = &g_q_h[qin][b][0][0];
    const __nv_bfloat16* ql = &g_q_l[qin][b][0][0];
    const __nv_bfloat16* kh = &g_kv_h[kin][b][0][0];
    const __nv_bfloat16* kl = &g_kv_l[kin][b][0][0];

    int qhalf = tid >> 8, qt = tid & 255;
    int qd = qt >> 2, qch = (qt & 3) * 16;
    const __nv_bfloat16* qsrc = (qhalf ? ql : qh) + (size_t)(h * 64 + qd) * NP1 + qch;
    uint32_t qdst = sb + (qhalf ? AQL4 : AQH4) + (uint32_t)(qd * QLD4 + qch) * 2;

#pragma unroll
    for (int u = 0; u < 4; u++) {
        int idx = tid + u * 512;
        int d = idx >> 5, ch = (idx & 31) * 8;
        size_t gk = (size_t)(h * 64 + d) * NP2 + ch;
        size_t gv = (size_t)(NINNER + h * 64 + d) * NP2 + ch;
        uint32_t so = (uint32_t)(d * KLD4 + ch) * 2;
        cpa16(sb + AKH4 + so, kh + gk);
        cpa16(sb + AKL4 + so, kl + gk);
        cpa16(sb + AVH4 + so, kh + gv);
        cpa16(sb + AVL4 + so, kl + gv);
    }
    cpa16(qdst, qsrc);
    cpa16(qdst + 16, qsrc + 8);
    CP_COMMIT();

    int rA = wr * 16 + (lane >> 2);
    int rB = rA + 8;

    for (int it = 0; it < 16; it++) {
        CP_WAIT0();
        __syncthreads();
        int i0 = it * 64;

        float acc[8][4];
#pragma unroll
        for (int i = 0; i < 8; i++)
#pragma unroll
            for (int k = 0; k < 4; k++) acc[i][k] = 0.f;

#pragma unroll
        for (int kk = 0; kk < 4; kk++) {
            uint32_t ah[4], al[4];
            uint32_t krow = (uint32_t)(kk*16 + (lane & 7) + ((lane >> 1) & 8));
            uint32_t acol = (uint32_t)(wr*16 + (lane & 8));
            uint32_t aaddr = sb + AQH4 + (krow * QLD4 + acol) * 2;
            ldmx4t(ah, aaddr);
            ldmx4t(al, aaddr + (AQL4 - AQH4));
#pragma unroll
            for (int ni2 = 0; ni2 < 4; ni2++) {
                uint32_t bhf[4], blf[4];
                uint32_t baddr = sb + AKH4 + (uint32_t)((kk*16 + (lane & 15)) * KLD4
                                                        + wc*64 + ni2*16 + ((lane & 16) >> 1)) * 2;
                ldmx4t(bhf, baddr);
                ldmx4t(blf, baddr + (AKL4 - AKH4));
                mma16816(acc[ni2*2],   ah, &bhf[0]);
                mma16816(acc[ni2*2],   ah, &blf[0]);
                mma16816(acc[ni2*2],   al, &bhf[0]);
                mma16816(acc[ni2*2+1], ah, &bhf[2]);
                mma16816(acc[ni2*2+1], ah, &blf[2]);
                mma16816(acc[ni2*2+1], al, &bhf[2]);
            }
        }
        __syncthreads();

        if (it + 1 < 16) {
            const __nv_bfloat16* nq = qsrc + (it + 1) * 64;
            cpa16(qdst, nq);
            cpa16(qdst + 16, nq + 8);
            CP_COMMIT();
        }

#pragma unroll
        for (int ni = 0; ni < 8; ni++)
#pragma unroll
            for (int k = 0; k < 4; k++) acc[ni][k] *= 0.125f;

        float mA = -1e30f, mB = -1e30f;
#pragma unroll
        for (int ni = 0; ni < 8; ni++) {
            mA = fmaxf(mA, fmaxf(acc[ni][0], acc[ni][1]));
            mB = fmaxf(mB, fmaxf(acc[ni][2], acc[ni][3]));
        }
        mA = fmaxf(mA, __shfl_xor_sync(0xffffffffu, mA, 1));
        mA = fmaxf(mA, __shfl_xor_sync(0xffffffffu, mA, 2));
        mB = fmaxf(mB, __shfl_xor_sync(0xffffffffu, mB, 1));
        mB = fmaxf(mB, __shfl_xor_sync(0xffffffffu, mB, 2));
        if ((lane & 3) == 0) { red_m[rA * 4 + wc] = mA; red_m[rB * 4 + wc] = mB; }
        __syncthreads();
        mA = fmaxf(fmaxf(red_m[rA*4], red_m[rA*4+1]), fmaxf(red_m[rA*4+2], red_m[rA*4+3]));
        mB = fmaxf(fmaxf(red_m[rB*4], red_m[rB*4+1]), fmaxf(red_m[rB*4+2], red_m[rB*4+3]));

        float sA = 0.f, sB = 0.f;
#pragma unroll
        for (int ni = 0; ni < 8; ni++) {
            acc[ni][0] = __expf(acc[ni][0] - mA);
            acc[ni][1] = __expf(acc[ni][1] - mA);
            acc[ni][2] = __expf(acc[ni][2] - mB);
            acc[ni][3] = __expf(acc[ni][3] - mB);
            sA += acc[ni][0] + acc[ni][1];
            sB += acc[ni][2] + acc[ni][3];
        }
        sA += __shfl_xor_sync(0xffffffffu, sA, 1);
        sA += __shfl_xor_sync(0xffffffffu, sA, 2);
        sB += __shfl_xor_sync(0xffffffffu, sB, 1);
        sB += __shfl_xor_sync(0xffffffffu, sB, 2);
        if ((lane & 3) == 0) { red_s[rA * 4 + wc] = sA; red_s[rB * 4 + wc] = sB; }

        // write UNNORMALIZED exp(P); normalization deferred to O staging
#pragma unroll
        for (int ni = 0; ni < 8; ni++) {
            int c = wc*64 + ni*8 + (lane & 3) * 2;
            put_hl2(Ph, Pl, rA * PLD4 + c, acc[ni][0], acc[ni][1]);
            put_hl2(Ph, Pl, rB * PLD4 + c, acc[ni][2], acc[ni][3]);
        }
        __syncthreads();

        float acc2[2][4];
#pragma unroll
        for (int i = 0; i < 2; i++)
#pragma unroll
            for (int k = 0; k < 4; k++) acc2[i][k] = 0.f;

#pragma unroll 4
        for (int kk = 0; kk < 16; kk++) {
            uint32_t ah[4], al[4];
            uint32_t aaddr = sb + APH4 + (uint32_t)((wr*16 + (lane & 15)) * PLD4
                                                    + kk*16 + (lane >> 4) * 8) * 2;
            ldmx4(ah, aaddr);
            ldmx4(al, aaddr + (APL4 - APH4));
            uint32_t bhf[4], blf[4];
            uint32_t baddr = sb + AVH4 + (uint32_t)((wc*16 + ((lane >> 4) & 1) * 8 + (lane & 7)) * KLD4
                                                    + kk*16 + ((lane >> 3) & 1) * 8) * 2;
            ldmx4(bhf, baddr);
            ldmx4(blf, baddr + (AVL4 - AVH4));
            mma16816(acc2[0], ah, &bhf[0]);
            mma16816(acc2[0], ah, &blf[0]);
            mma16816(acc2[0], al, &bhf[0]);
            mma16816(acc2[1], ah, &bhf[2]);
            mma16816(acc2[1], ah, &blf[2]);
            mma16816(acc2[1], al, &bhf[2]);
        }
        __syncthreads();

        float invA = 1.f / (red_s[rA*4] + red_s[rA*4+1] + red_s[rA*4+2] + red_s[rA*4+3]);
        float invB = 1.f / (red_s[rB*4] + red_s[rB*4+1] + red_s[rB*4+2] + red_s[rB*4+3]);
#pragma unroll
        for (int ni = 0; ni < 2; ni++) {
            int c = wc*16 + ni*8 + (lane & 3) * 2;
            O[rA * OLD4 + c]     = acc2[ni][0] * invA;
            O[rA * OLD4 + c + 1] = acc2[ni][1] * invA;
            O[rB * OLD4 + c]     = acc2[ni][2] * invB;
            O[rB * OLD4 + c + 1] = acc2[ni][3] * invB;
        }
        __syncthreads();
        {
            int d = tid >> 3, ip = (tid & 7) * 8;
            __nv_bfloat16* aoh = &g_ao_h[qin][b][h * 64 + d][i0 + ip];
            __nv_bfloat16* aol = &g_ao_l[qin][b][h * 64 + d][i0 + ip];
#pragma unroll
            for (int u = 0; u < 8; u += 2) {
                float v0 = O[(ip + u) * OLD4 + d];
                float v1 = O[(ip + u + 1) * OLD4 + d];
                put_hl2(aoh, aol, u, v0, v1);
            }
        }
    }
}

// ---------------- launch ----------------
extern "C" void kernel_launch(void* const* d_in, const int* in_sizes, int n_in,
                              void* d_out, int out_size)
{
    const float* x      = (const float*)d_in[0];
    const float* y      = (const float*)d_in[1];
    const float* q_dw_w = (const float*)d_in[2];
    const float* q_g    = (const float*)d_in[3];
    const float* q_b    = (const float*)d_in[4];
    const float* q_m    = (const float*)d_in[5];
    const float* q_v    = (const float*)d_in[6];
    const float* q_pw   = (const float*)d_in[7];
    const float* kv_dw_w= (const float*)d_in[8];
    const float* kv_g   = (const float*)d_in[9];
    const float* kv_b   = (const float*)d_in[10];
    const float* kv_m   = (const float*)d_in[11];
    const float* kv_v   = (const float*)d_in[12];
    const float* kv_pw  = (const float*)d_in[13];
    const float* out_w  = (const float*)d_in[14];
    const float* out_b  = (const float*)d_in[15];
    float* out = (float*)d_out;

    __nv_bfloat16 *wq_h, *wq_l, *wkv_h, *wkv_l, *wo_h, *wo_l;
    __nv_bfloat16 *hq_h, *hq_l, *hkv_h, *hkv_l, *q_hp, *q_lp, *kv_hp, *kv_lp, *ao_h, *ao_l;
    cudaGetSymbolAddress((void**)&wq_h,  g_wq_h);  cudaGetSymbolAddress((void**)&wq_l,  g_wq_l);
    cudaGetSymbolAddress((void**)&wkv_h, g_wkv_h); cudaGetSymbolAddress((void**)&wkv_l, g_wkv_l);
    cudaGetSymbolAddress((void**)&wo_h,  g_wo_h);  cudaGetSymbolAddress((void**)&wo_l,  g_wo_l);
    cudaGetSymbolAddress((void**)&hq_h,  g_hq_h);  cudaGetSymbolAddress((void**)&hq_l,  g_hq_l);
    cudaGetSymbolAddress((void**)&hkv_h, g_hkv_h); cudaGetSymbolAddress((void**)&hkv_l, g_hkv_l);
    cudaGetSymbolAddress((void**)&q_hp,  g_q_h);   cudaGetSymbolAddress((void**)&q_lp,  g_q_l);
    cudaGetSymbolAddress((void**)&kv_hp, g_kv_h);  cudaGetSymbolAddress((void**)&kv_lp, g_kv_l);
    cudaGetSymbolAddress((void**)&ao_h,  g_ao_h);  cudaGetSymbolAddress((void**)&ao_l,  g_ao_l);

    size_t szHQ  = (size_t)NB * NC * NP1;
    size_t szHKV = (size_t)NB * NC * NP2;
    size_t szQ   = (size_t)NB * NINNER * NP1;
    size_t szKV  = (size_t)NB * 2 * NINNER * NP2;

    static cudaStream_t s1 = nullptr, s2 = nullptr;
    static cudaEvent_t e_fork, e_cvt, e_dw0, e_dw1, e_q0, e_q1, e_kv1, e_at0, e_at1;
    if (!s1) {
        cudaStreamCreateWithFlags(&s1, cudaStreamNonBlocking);
        cudaStreamCreateWithFlags(&s2, cudaStreamNonBlocking);
        cudaEventCreateWithFlags(&e_fork, cudaEventDisableTiming);
        cudaEventCreateWithFlags(&e_cvt,  cudaEventDisableTiming);
        cudaEventCreateWithFlags(&e_dw0,  cudaEventDisableTiming);
        cudaEventCreateWithFlags(&e_dw1,  cudaEventDisableTiming);
        cudaEventCreateWithFlags(&e_q0,   cudaEventDisableTiming);
        cudaEventCreateWithFlags(&e_q1,   cudaEventDisableTiming);
        cudaEventCreateWithFlags(&e_kv1,  cudaEventDisableTiming);
        cudaEventCreateWithFlags(&e_at0,  cudaEventDisableTiming);
        cudaEventCreateWithFlags(&e_at1,  cudaEventDisableTiming);
        cudaFuncSetAttribute(mm_attn4, cudaFuncAttributeMaxDynamicSharedMemorySize, ATT_SM4);
        cudaFuncSetAttribute(mm_gemm2, cudaFuncAttributeMaxDynamicSharedMemorySize, GSM2);
    }

    cudaEventRecord(e_fork, 0);
    cudaStreamWaitEvent(s1, e_fork, 0);
    cudaStreamWaitEvent(s2, e_fork, 0);

    // s1: weight conversions
    cvt_hl_kernel<<<(NINNER * NC / 2 + 255) / 256, 256, 0, s1>>>(q_pw,  wq_h,  wq_l,  NINNER * NC / 2);
    cvt_hl_kernel<<<(2 * NINNER * NC / 2 + 255) / 256, 256, 0, s1>>>(kv_pw, wkv_h, wkv_l, 2 * NINNER * NC / 2);
    cvt_hl_kernel<<<(NC * NINNER / 2 + 255) / 256, 256, 0, s1>>>(out_w, wo_h,  wo_l,  NC * NINNER / 2);
    cudaEventRecord(e_cvt, s1);

    // stream0: dwbn per input
    dwbn_fused<<<NB * NC, 256>>>(x, y, q_dw_w, q_g, q_b, q_m, q_v,
                                 kv_dw_w, kv_g, kv_b, kv_m, kv_v, 0);
    cudaEventRecord(e_dw0, 0);
    dwbn_fused<<<NB * NC, 256>>>(x, y, q_dw_w, q_g, q_b, q_m, q_v,
                                 kv_dw_w, kv_g, kv_b, kv_m, kv_v, 1);
    cudaEventRecord(e_dw1, 0);

    // s1: kv-proj inp0 then inp1
    cudaStreamWaitEvent(s1, e_dw0, 0);
    mm_gemm2<<<dim3(NP2 / 128, (2 * NINNER) / 128, NB), 256, GSM2, s1>>>(
        wkv_h, wkv_l, hkv_h, hkv_l, kv_hp, kv_lp, nullptr, nullptr,
        2 * NINNER, NC, NP2);
    cudaStreamWaitEvent(s1, e_dw1, 0);
    mm_gemm2<<<dim3(NP2 / 128, (2 * NINNER) / 128, NB), 256, GSM2, s1>>>(
        wkv_h, wkv_l, hkv_h + szHKV, hkv_l + szHKV, kv_hp + szKV, kv_lp + szKV,
        nullptr, nullptr, 2 * NINNER, NC, NP2);
    cudaEventRecord(e_kv1, s1);

    // stream0: q-proj inp0 then inp1 (need weight cvt)
    cudaStreamWaitEvent(0, e_cvt, 0);
    mm_gemm2<<<dim3(NP1 / 128, NINNER / 128, NB), 256, GSM2>>>(
        wq_h, wq_l, hq_h, hq_l, q_hp, q_lp, nullptr, nullptr,
        NINNER, NC, NP1);
    cudaEventRecord(e_q0, 0);
    mm_gemm2<<<dim3(NP1 / 128, NINNER / 128, NB), 256, GSM2>>>(
        wq_h, wq_l, hq_h + szHQ, hq_l + szHQ, q_hp + szQ, q_lp + szQ,
        nullptr, nullptr, NINNER, NC, NP1);
    cudaEventRecord(e_q1, 0);

    // s2: attn dir0 (needs q-proj0 + kv-proj1)
    cudaStreamWaitEvent(s2, e_q0, 0);
    cudaStreamWaitEvent(s2, e_kv1, 0);
    mm_attn4<<<NB * 8, 512, ATT_SM4, s2>>>(0);
    cudaEventRecord(e_at0, s2);

    // s1: attn dir1 (needs q-proj1; kv-proj0 implicit on s1)
    cudaStreamWaitEvent(s1, e_q1, 0);
    mm_attn4<<<NB * 8, 512, ATT_SM4, s1>>>(1);
    cudaEventRecord(e_at1, s1);

    // stream0: output projection after both attns
    cudaStreamWaitEvent(0, e_at0, 0);
    cudaStreamWaitEvent(0, e_at1, 0);
    mm_gemm2<<<dim3(NP1 / 128, NC / 128, 2 * NB), 256, GSM2>>>(
        wo_h, wo_l, ao_h, ao_l, nullptr, nullptr, out, out_b,
        NC, NINNER, NP1);
}

// round 15
// speedup vs baseline: 1.0627x; 1.0075x over previous
#include <cuda_runtime.h>
#include <cuda_bf16.h>
#include <stdint.h>
#include <math.h>

#define NB 8
#define NC 256
#define NP1 1024
#define NP2 256
#define NINNER 512
#define BN_EPS 1e-5f

// ---------------- bf16 hi/lo scratch ----------------
__device__ __nv_bfloat16 g_hq_h [2][NB][NC][NP1],      g_hq_l [2][NB][NC][NP1];
__device__ __nv_bfloat16 g_hkv_h[2][NB][NC][NP2],      g_hkv_l[2][NB][NC][NP2];
__device__ __nv_bfloat16 g_q_h  [2][NB][NINNER][NP1],  g_q_l  [2][NB][NINNER][NP1];
__device__ __nv_bfloat16 g_kv_h [2][NB][2*NINNER][NP2],g_kv_l [2][NB][2*NINNER][NP2];
__device__ __nv_bfloat16 g_ao_h [2][NB][NINNER][NP1],  g_ao_l [2][NB][NINNER][NP1];
__device__ __nv_bfloat16 g_wq_h [NINNER*NC],   g_wq_l [NINNER*NC];
__device__ __nv_bfloat16 g_wkv_h[2*NINNER*NC], g_wkv_l[2*NINNER*NC];
__device__ __nv_bfloat16 g_wo_h [NC*NINNER],   g_wo_l [NC*NINNER];

// ---------------- helpers ----------------
__device__ __forceinline__ uint32_t smem_u32(const void* p){
    uint32_t a;
    asm("{ .reg .u64 t; cvta.to.shared.u64 t, %1; cvt.u32.u64 %0, t; }" : "=r"(a) : "l"(p));
    return a;
}
__device__ __forceinline__ void ldmx4(uint32_t* r, uint32_t a){
    asm volatile("ldmatrix.sync.aligned.m8n8.x4.shared.b16 {%0,%1,%2,%3}, [%4];"
        : "=r"(r[0]),"=r"(r[1]),"=r"(r[2]),"=r"(r[3]) : "r"(a) : "memory");
}
__device__ __forceinline__ void ldmx4t(uint32_t* r, uint32_t a){
    asm volatile("ldmatrix.sync.aligned.m8n8.x4.trans.shared.b16 {%0,%1,%2,%3}, [%4];"
        : "=r"(r[0]),"=r"(r[1]),"=r"(r[2]),"=r"(r[3]) : "r"(a) : "memory");
}
__device__ __forceinline__ void mma16816(float* c, const uint32_t* a, const uint32_t* b){
    asm volatile("mma.sync.aligned.m16n8k16.row.col.f32.bf16.bf16.f32 "
        "{%0,%1,%2,%3}, {%4,%5,%6,%7}, {%8,%9}, {%0,%1,%2,%3};"
        : "+f"(c[0]),"+f"(c[1]),"+f"(c[2]),"+f"(c[3])
        : "r"(a[0]),"r"(a[1]),"r"(a[2]),"r"(a[3]),"r"(b[0]),"r"(b[1]));
}
__device__ __forceinline__ void cpa16(uint32_t s, const void* g){
    asm volatile("cp.async.cg.shared.global [%0], [%1], 16;" :: "r"(s), "l"(g));
}
#define CP_COMMIT() asm volatile("cp.async.commit_group;" ::: "memory")
#define CP_WAIT0()  asm volatile("cp.async.wait_group 0;" ::: "memory")
#define CP_WAIT1()  asm volatile("cp.async.wait_group 1;" ::: "memory")

// hi/lo split, packed converts + bit reconstruction (bit-identical to scalar path)
__device__ __forceinline__ void put_hl2(__nv_bfloat16* bh, __nv_bfloat16* bl, int idx, float v0, float v1){
    uint32_t hp;
    asm("cvt.rn.bf16x2.f32 %0, %1, %2;" : "=r"(hp) : "f"(v1), "f"(v0));
    float h0 = __uint_as_float(hp << 16);
    float h1 = __uint_as_float(hp & 0xFFFF0000u);
    uint32_t lp;
    float l0 = v0 - h0, l1 = v1 - h1;
    asm("cvt.rn.bf16x2.f32 %0, %1, %2;" : "=r"(lp) : "f"(l1), "f"(l0));
    *(uint32_t*)(bh + idx) = hp;
    *(uint32_t*)(bl + idx) = lp;
}
__device__ __forceinline__ void put_hl4(__nv_bfloat16* bh, __nv_bfloat16* bl, int idx,
                                        float v0, float v1, float v2, float v3){
    uint32_t hp0, hp1, lp0, lp1;
    asm("cvt.rn.bf16x2.f32 %0, %1, %2;" : "=r"(hp0) : "f"(v1), "f"(v0));
    asm("cvt.rn.bf16x2.f32 %0, %1, %2;" : "=r"(hp1) : "f"(v3), "f"(v2));
    float h0 = __uint_as_float(hp0 << 16), h1 = __uint_as_float(hp0 & 0xFFFF0000u);
    float h2 = __uint_as_float(hp1 << 16), h3 = __uint_as_float(hp1 & 0xFFFF0000u);
    asm("cvt.rn.bf16x2.f32 %0, %1, %2;" : "=r"(lp0) : "f"(v1 - h1), "f"(v0 - h0));
    asm("cvt.rn.bf16x2.f32 %0, %1, %2;" : "=r"(lp1) : "f"(v3 - h3), "f"(v2 - h2));
    *(uint2*)(bh + idx) = make_uint2(hp0, hp1);
    *(uint2*)(bl + idx) = make_uint2(lp0, lp1);
}
__device__ __forceinline__ void put_hl(__nv_bfloat16* bh, __nv_bfloat16* bl, int idx, float v){
    __nv_bfloat16 h = __float2bfloat16(v);
    bh[idx] = h;
    float hf = __uint_as_float(((uint32_t)__bfloat16_as_ushort(h)) << 16);
    bl[idx] = __float2bfloat16(v - hf);
}

// ---------------- weight fp32 -> hi/lo ----------------
__global__ void cvt_hl_kernel(const float* __restrict__ src, __nv_bfloat16* __restrict__ h,
                              __nv_bfloat16* __restrict__ l, int n2){
    int i = blockIdx.x * 256 + threadIdx.x;
    if (i < n2) {
        float2 v = *(const float2*)(src + i * 2);
        put_hl2(h, l, i * 2, v.x, v.y);
    }
}

// ---------------- fused depthwise conv (s1 + s2) + BN, per-input ----------------
__global__ __launch_bounds__(256)
void dwbn_fused(const float* __restrict__ x0, const float* __restrict__ x1,
                const float* __restrict__ qw, const float* __restrict__ qg,
                const float* __restrict__ qb, const float* __restrict__ qm,
                const float* __restrict__ qv,
                const float* __restrict__ kw, const float* __restrict__ kg,
                const float* __restrict__ kb, const float* __restrict__ km,
                const float* __restrict__ kvv, int inp)
{
    int bc = blockIdx.x, c = bc & 255, b = bc >> 8;
    const float* in = (inp ? x1 : x0) + (size_t)bc * 1024;
    __shared__ float t[34][36];
    int tid = threadIdx.x;

    if (tid < 34) { t[0][tid] = 0.f; t[33][tid] = 0.f; }
    else if (tid < 66) { int r = tid - 33; t[r][0] = 0.f; t[r][33] = 0.f; }

    {
        int r = tid >> 3, q = (tid & 7) * 4;
        float4 v = *(const float4*)(in + r * 32 + q);
        t[r + 1][q + 1] = v.x; t[r + 1][q + 2] = v.y;
        t[r + 1][q + 3] = v.z; t[r + 1][q + 4] = v.w;
    }

    float qwr[9], kwr[9];
#pragma unroll
    for (int i = 0; i < 9; i++) { qwr[i] = qw[c * 9 + i]; kwr[i] = kw[c * 9 + i]; }
    float qs  = qg[c] * rsqrtf(qv[c] + BN_EPS);
    float qsh = qb[c] - qm[c] * qs;
    float ks  = kg[c] * rsqrtf(kvv[c] + BN_EPS);
    float ksh = kb[c] - km[c] * ks;
    __syncthreads();

    {
        int oy = tid >> 3, ox = (tid & 7) * 4;
        float o0 = 0.f, o1 = 0.f, o2 = 0.f, o3 = 0.f;
#pragma unroll
        for (int dy = 0; dy < 3; dy++) {
            float a0 = t[oy + dy][ox + 0], a1 = t[oy + dy][ox + 1], a2 = t[oy + dy][ox + 2];
            float a3 = t[oy + dy][ox + 3], a4 = t[oy + dy][ox + 4], a5 = t[oy + dy][ox + 5];
            float w0 = qwr[dy * 3], w1 = qwr[dy * 3 + 1], w2 = qwr[dy * 3 + 2];
            o0 += a0 * w0 + a1 * w1 + a2 * w2;
            o1 += a1 * w0 + a2 * w1 + a3 * w2;
            o2 += a2 * w0 + a3 * w1 + a4 * w2;
            o3 += a3 * w0 + a4 * w1 + a5 * w2;
        }
        o0 = o0 * qs + qsh; o1 = o1 * qs + qsh;
        o2 = o2 * qs + qsh; o3 = o3 * qs + qsh;
        put_hl4(&g_hq_h[inp][b][c][0], &g_hq_l[inp][b][c][0], oy * 32 + ox, o0, o1, o2, o3);
    }

    {
        int oy = tid >> 4, ox = tid & 15;
        float a = 0.f;
#pragma unroll
        for (int dy = 0; dy < 3; dy++)
#pragma unroll
            for (int dx = 0; dx < 3; dx++)
                a += t[oy * 2 + dy][ox * 2 + dx] * kwr[dy * 3 + dx];
        a = a * ks + ksh;
        put_hl(&g_hkv_h[inp][b][c][0], &g_hkv_l[inp][b][c][0], oy * 16 + ox, a);
    }
}

// ---------------- tensor-core GEMM (2-stage, 2 CTAs/SM) ----------------
#define ALD2 40
#define BLD2 136
#define A_H0 0
#define A_H1 10240
#define A_L0 20480
#define A_L1 30720
#define B_H0 40960
#define B_H1 49664
#define B_L0 58368
#define B_L1 67072
#define GSM2 75776
#define ELD 136
#define ELDF 136

__global__ __launch_bounds__(256, 2)
void mm_gemm2(const __nv_bfloat16* __restrict__ Ah, const __nv_bfloat16* __restrict__ Al,
              const __nv_bfloat16* __restrict__ Bh, const __nv_bfloat16* __restrict__ Bl,
              __nv_bfloat16* __restrict__ Ch, __nv_bfloat16* __restrict__ Cl,
              float* __restrict__ Cf, const float* __restrict__ bias,
              int Mtot, int K, int P)
{
    extern __shared__ char sm[];
    uint32_t sb = smem_u32(sm);
    int tid = threadIdx.x, lane = tid & 31, wid = tid >> 5;
    int wr = wid >> 1, wc = wid & 1;
    int m0 = blockIdx.y * 128, n0 = blockIdx.x * 128;
    size_t zoff = (size_t)blockIdx.z * K * P;
    const __nv_bfloat16* Bhz = Bh + zoff;
    const __nv_bfloat16* Blz = Bl + zoff;

    float acc[2][8][4];
#pragma unroll
    for (int i = 0; i < 2; i++)
#pragma unroll
        for (int j = 0; j < 8; j++)
#pragma unroll
            for (int k = 0; k < 4; k++) acc[i][j][k] = 0.f;

    int niter = K >> 5;

#define LOAD_STAGE(st, k0) do { \
    uint32_t aH = sb + ((st) ? A_H1 : A_H0); \
    uint32_t aL = sb + ((st) ? A_L1 : A_L0); \
    uint32_t bH = sb + ((st) ? B_H1 : B_H0); \
    uint32_t bL = sb + ((st) ? B_L1 : B_L0); \
    _Pragma("unroll") \
    for (int u = 0; u < 2; u++) { \
        int idx = tid + u * 256; \
        int row = idx >> 2, ch = (idx & 3) * 8; \
        size_t go = (size_t)(m0 + row) * K + (k0) + ch; \
        uint32_t so = (uint32_t)(row * ALD2 + ch) * 2; \
        cpa16(aH + so, Ah + go); \
        cpa16(aL + so, Al + go); \
    } \
    _Pragma("unroll") \
    for (int u = 0; u < 2; u++) { \
        int idx = tid + u * 256; \
        int row = idx >> 4, ch = (idx & 15) * 8; \
        size_t go = (size_t)((k0) + row) * P + n0 + ch; \
        uint32_t so = (uint32_t)(row * BLD2 + ch) * 2; \
        cpa16(bH + so, Bhz + go); \
        cpa16(bL + so, Blz + go); \
    } \
} while (0)

    LOAD_STAGE(0, 0);
    CP_COMMIT();

    for (int it = 0; it < niter; it++) {
        if (it + 1 < niter) { LOAD_STAGE((it + 1) & 1, (it + 1) << 5); CP_COMMIT(); CP_WAIT1(); }
        else CP_WAIT0();
        __syncthreads();

        uint32_t aHb = sb + ((it & 1) ? A_H1 : A_H0);
        uint32_t bHb = sb + ((it & 1) ? B_H1 : B_H0);
#pragma unroll
        for (int kk = 0; kk < 2; kk++) {
            uint32_t ah[2][4], al[2][4];
#pragma unroll
            for (int mi = 0; mi < 2; mi++) {
                uint32_t aaddr = aHb + (uint32_t)((wr*32 + mi*16 + (lane & 15)) * ALD2
                                                  + kk*16 + (lane >> 4) * 8) * 2;
                ldmx4(ah[mi], aaddr);
                ldmx4(al[mi], aaddr + 20480u);
            }
#pragma unroll
            for (int ni2 = 0; ni2 < 4; ni2++) {
                uint32_t bh[4], bl[4];
                uint32_t baddr = bHb + (uint32_t)((kk*16 + (lane & 15)) * BLD2
                                                  + wc*64 + ni2*16 + ((lane & 16) >> 1)) * 2;
                ldmx4t(bh, baddr);
                ldmx4t(bl, baddr + 17408u);
#pragma unroll
                for (int mi = 0; mi < 2; mi++) {
                    mma16816(acc[mi][ni2*2],   ah[mi], &bh[0]);
                    mma16816(acc[mi][ni2*2],   ah[mi], &bl[0]);
                    mma16816(acc[mi][ni2*2],   al[mi], &bh[0]);
                    mma16816(acc[mi][ni2*2+1], ah[mi], &bh[2]);
                    mma16816(acc[mi][ni2*2+1], ah[mi], &bl[2]);
                    mma16816(acc[mi][ni2*2+1], al[mi], &bh[2]);
                }
            }
        }
        __syncthreads();
    }

    if (Cf) {
        float* Ef = (float*)sm;
        float* Cp = Cf + (size_t)blockIdx.z * Mtot * P;
#pragma unroll
        for (int mi = 0; mi < 2; mi++) {
            int row = wr*32 + mi*16 + (lane >> 2);
            float b0 = bias ? bias[m0 + row] : 0.f;
            float b1 = bias ? bias[m0 + row + 8] : 0.f;
#pragma unroll
            for (int ni = 0; ni < 8; ni++) {
                int col = wc*64 + ni*8 + (lane & 3) * 2;
                *(float2*)&Ef[row * ELDF + col] =
                    make_float2(acc[mi][ni][0] + b0, acc[mi][ni][1] + b0);
                *(float2*)&Ef[(row + 8) * ELDF + col] =
                    make_float2(acc[mi][ni][2] + b1, acc[mi][ni][3] + b1);
            }
        }
        __syncthreads();
#pragma unroll
        for (int u = 0; u < 16; u++) {
            int linear = tid + u * 256;
            int row = linear >> 5, c4 = (linear & 31) * 4;
            *(float4*)&Cp[(size_t)(m0 + row) * P + n0 + c4] =
                *(const float4*)&Ef[row * ELDF + c4];
        }
    } else {
        __nv_bfloat16* Eh = (__nv_bfloat16*)sm;
        __nv_bfloat16* El = (__nv_bfloat16*)(sm + 128 * ELD * 2);
#pragma unroll
        for (int mi = 0; mi < 2; mi++) {
            int row = wr*32 + mi*16 + (lane >> 2);
#pragma unroll
            for (int ni = 0; ni < 8; ni++) {
                int col = wc*64 + ni*8 + (lane & 3) * 2;
                put_hl2(Eh, El, row * ELD + col, acc[mi][ni][0], acc[mi][ni][1]);
                put_hl2(Eh, El, (row + 8) * ELD + col, acc[mi][ni][2], acc[mi][ni][3]);
            }
        }
        __syncthreads();
        __nv_bfloat16* Chz = Ch + (size_t)blockIdx.z * Mtot * P;
        __nv_bfloat16* Clz = Cl + (size_t)blockIdx.z * Mtot * P;
#pragma unroll
        for (int u = 0; u < 8; u++) {
            int linear = tid + u * 256;
            int row = linear >> 4, c8 = (linear & 15) * 8;
            size_t go = (size_t)(m0 + row) * P + n0 + c8;
            *(uint4*)&Chz[go] = *(const uint4*)&Eh[row * ELD + c8];
            *(uint4*)&Clz[go] = *(const uint4*)&El[row * ELD + c8];
        }
    }
}

// ---------------- fused attention v7: split i-range (8 tiles/CTA), per-dir ----------------
#define QLD4 72
#define KLD4 264
#define PLD4 264
#define OLD4 65
#define AQH4 0
#define AQL4 9216
#define AKH4 18432
#define AKL4 52224
#define AVH4 86016
#define AVL4 119808
#define APH4 153600
#define APL4 187392
#define AREDM 221184
#define AREDS 222208
#define ATT_SM4 223232

__global__ __launch_bounds__(512)
void mm_attn4(int dir)
{
    extern __shared__ char sm[];
    uint32_t sb = smem_u32(sm);
    float* red_m = (float*)(sm + AREDM);
    float* red_s = (float*)(sm + AREDS);
    float* O   = (float*)(sm + APH4);
    __nv_bfloat16* Ph = (__nv_bfloat16*)(sm + APH4);
    __nv_bfloat16* Pl = (__nv_bfloat16*)(sm + APL4);

    int tid = threadIdx.x, lane = tid & 31, wid = tid >> 5;
    int bh = blockIdx.x;
    int b = bh >> 3, h = bh & 7;
    int it0 = blockIdx.y * 8;          // half of the i-range
    int qin = dir, kin = dir ^ 1;
    int wr = wid >> 2, wc = wid & 3;

    const __nv_bfloat16* qh = &g_q_h[qin][b][0][0];
    const __nv_bfloat16* ql = &g_q_l[qin][b][0][0];
    const __nv_bfloat16* kh = &g_kv_h[kin][b][0][0];
    const __nv_bfloat16* kl = &g_kv_l[kin][b][0][0];

    int qhalf = tid >> 8, qt = tid & 255;
    int qd = qt >> 2, qch = (qt & 3) * 16;
    const __nv_bfloat16* qsrc = (qhalf ? ql : qh) + (size_t)(h * 64 + qd) * NP1 + it0 * 64 + qch;
    uint32_t qdst = sb + (qhalf ? AQL4 : AQH4) + (uint32_t)(qd * QLD4 + qch) * 2;

#pragma unroll
    for (int u = 0; u < 4; u++) {
        int idx = tid + u * 512;
        int d = idx >> 5, ch = (idx & 31) * 8;
        size_t gk = (size_t)(h * 64 + d) * NP2 + ch;
        size_t gv = (size_t)(NINNER + h * 64 + d) * NP2 + ch;
        uint32_t so = (uint32_t)(d * KLD4 + ch) * 2;
        cpa16(sb + AKH4 + so, kh + gk);
        cpa16(sb + AKL4 + so, kl + gk);
        cpa16(sb + AVH4 + so, kh + gv);
        cpa16(sb + AVL4 + so, kl + gv);
    }
    cpa16(qdst, qsrc);
    cpa16(qdst + 16, qsrc + 8);
    CP_COMMIT();

    int rA = wr * 16 + (lane >> 2);
    int rB = rA + 8;

    for (int lt = 0; lt < 8; lt++) {
        CP_WAIT0();
        __syncthreads();
        int i0 = (it0 + lt) * 64;

        float acc[8][4];
#pragma unroll
        for (int i = 0; i < 8; i++)
#pragma unroll
            for (int k = 0; k < 4; k++) acc[i][k] = 0.f;

#pragma unroll
        for (int kk = 0; kk < 4; kk++) {
            uint32_t ah[4], al[4];
            uint32_t krow = (uint32_t)(kk*16 + (lane & 7) + ((lane >> 1) & 8));
            uint32_t acol = (uint32_t)(wr*16 + (lane & 8));
            uint32_t aaddr = sb + AQH4 + (krow * QLD4 + acol) * 2;
            ldmx4t(ah, aaddr);
            ldmx4t(al, aaddr + (AQL4 - AQH4));
#pragma unroll
            for (int ni2 = 0; ni2 < 4; ni2++) {
                uint32_t bhf[4], blf[4];
                uint32_t baddr = sb + AKH4 + (uint32_t)((kk*16 + (lane & 15)) * KLD4
                                                        + wc*64 + ni2*16 + ((lane & 16) >> 1)) * 2;
                ldmx4t(bhf, baddr);
                ldmx4t(blf, baddr + (AKL4 - AKH4));
                mma16816(acc[ni2*2],   ah, &bhf[0]);
                mma16816(acc[ni2*2],   ah, &blf[0]);
                mma16816(acc[ni2*2],   al, &bhf[0]);
                mma16816(acc[ni2*2+1], ah, &bhf[2]);
                mma16816(acc[ni2*2+1], ah, &blf[2]);
                mma16816(acc[ni2*2+1], al, &bhf[2]);
            }
        }
        __syncthreads();

        if (lt + 1 < 8) {
            const __nv_bfloat16* nq = qsrc + (lt + 1) * 64;
            cpa16(qdst, nq);
            cpa16(qdst + 16, nq + 8);
            CP_COMMIT();
        }

#pragma unroll
        for (int ni = 0; ni < 8; ni++)
#pragma unroll
            for (int k = 0; k < 4; k++) acc[ni][k] *= 0.125f;

        float mA = -1e30f, mB = -1e30f;
#pragma unroll
        for (int ni = 0; ni < 8; ni++) {
            mA = fmaxf(mA, fmaxf(acc[ni][0], acc[ni][1]));
            mB = fmaxf(mB, fmaxf(acc[ni][2], acc[ni][3]));
        }
        mA = fmaxf(mA, __shfl_xor_sync(0xffffffffu, mA, 1));
        mA = fmaxf(mA, __shfl_xor_sync(0xffffffffu, mA, 2));
        mB = fmaxf(mB, __shfl_xor_sync(0xffffffffu, mB, 1));
        mB = fmaxf(mB, __shfl_xor_sync(0xffffffffu, mB, 2));
        if ((lane & 3) == 0) { red_m[rA * 4 + wc] = mA; red_m[rB * 4 + wc] = mB; }
        __syncthreads();
        mA = fmaxf(fmaxf(red_m[rA*4], red_m[rA*4+1]), fmaxf(red_m[rA*4+2], red_m[rA*4+3]));
        mB = fmaxf(fmaxf(red_m[rB*4], red_m[rB*4+1]), fmaxf(red_m[rB*4+2], red_m[rB*4+3]));

        float sA = 0.f, sB = 0.f;
#pragma unroll
        for (int ni = 0; ni < 8; ni++) {
            acc[ni][0] = __expf(acc[ni][0] - mA);
            acc[ni][1] = __expf(acc[ni][1] - mA);
            acc[ni][2] = __expf(acc[ni][2] - mB);
            acc[ni][3] = __expf(acc[ni][3] - mB);
            sA += acc[ni][0] + acc[ni][1];
            sB += acc[ni][2] + acc[ni][3];
        }
        sA += __shfl_xor_sync(0xffffffffu, sA, 1);
        sA += __shfl_xor_sync(0xffffffffu, sA, 2);
        sB += __shfl_xor_sync(0xffffffffu, sB, 1);
        sB += __shfl_xor_sync(0xffffffffu, sB, 2);
        if ((lane & 3) == 0) { red_s[rA * 4 + wc] = sA; red_s[rB * 4 + wc] = sB; }

        // unnormalized exp(P); normalize at O staging
#pragma unroll
        for (int ni = 0; ni < 8; ni++) {
            int c = wc*64 + ni*8 + (lane & 3) * 2;
            put_hl2(Ph, Pl, rA * PLD4 + c, acc[ni][0], acc[ni][1]);
            put_hl2(Ph, Pl, rB * PLD4 + c, acc[ni][2], acc[ni][3]);
        }
        __syncthreads();

        float acc2[2][4];
#pragma unroll
        for (int i = 0; i < 2; i++)
#pragma unroll
            for (int k = 0; k < 4; k++) acc2[i][k] = 0.f;

#pragma unroll 4
        for (int kk = 0; kk < 16; kk++) {
            uint32_t ah[4], al[4];
            uint32_t aaddr = sb + APH4 + (uint32_t)((wr*16 + (lane & 15)) * PLD4
                                                    + kk*16 + (lane >> 4) * 8) * 2;
            ldmx4(ah, aaddr);
            ldmx4(al, aaddr + (APL4 - APH4));
            uint32_t bhf[4], blf[4];
            uint32_t baddr = sb + AVH4 + (uint32_t)((wc*16 + ((lane >> 4) & 1) * 8 + (lane & 7)) * KLD4
                                                    + kk*16 + ((lane >> 3) & 1) * 8) * 2;
            ldmx4(bhf, baddr);
            ldmx4(blf, baddr + (AVL4 - AVH4));
            mma16816(acc2[0], ah, &bhf[0]);
            mma16816(acc2[0], ah, &blf[0]);
            mma16816(acc2[0], al, &bhf[0]);
            mma16816(acc2[1], ah, &bhf[2]);
            mma16816(acc2[1], ah, &blf[2]);
            mma16816(acc2[1], al, &bhf[2]);
        }
        __syncthreads();

        float invA = 1.f / (red_s[rA*4] + red_s[rA*4+1] + red_s[rA*4+2] + red_s[rA*4+3]);
        float invB = 1.f / (red_s[rB*4] + red_s[rB*4+1] + red_s[rB*4+2] + red_s[rB*4+3]);
#pragma unroll
        for (int ni = 0; ni < 2; ni++) {
            int c = wc*16 + ni*8 + (lane & 3) * 2;
            O[rA * OLD4 + c]     = acc2[ni][0] * invA;
            O[rA * OLD4 + c + 1] = acc2[ni][1] * invA;
            O[rB * OLD4 + c]     = acc2[ni][2] * invB;
            O[rB * OLD4 + c + 1] = acc2[ni][3] * invB;
        }
        __syncthreads();
        {
            int d = tid >> 3, ip = (tid & 7) * 8;
            __nv_bfloat16* aoh = &g_ao_h[qin][b][h * 64 + d][i0 + ip];
            __nv_bfloat16* aol = &g_ao_l[qin][b][h * 64 + d][i0 + ip];
#pragma unroll
            for (int u = 0; u < 8; u += 2) {
                float v0 = O[(ip + u) * OLD4 + d];
                float v1 = O[(ip + u + 1) * OLD4 + d];
                put_hl2(aoh, aol, u, v0, v1);
            }
        }
    }
}

// ---------------- launch ----------------
extern "C" void kernel_launch(void* const* d_in, const int* in_sizes, int n_in,
                              void* d_out, int out_size)
{
    const float* x      = (const float*)d_in[0];
    const float* y      = (const float*)d_in[1];
    const float* q_dw_w = (const float*)d_in[2];
    const float* q_g    = (const float*)d_in[3];
    const float* q_b    = (const float*)d_in[4];
    const float* q_m    = (const float*)d_in[5];
    const float* q_v    = (const float*)d_in[6];
    const float* q_pw   = (const float*)d_in[7];
    const float* kv_dw_w= (const float*)d_in[8];
    const float* kv_g   = (const float*)d_in[9];
    const float* kv_b   = (const float*)d_in[10];
    const float* kv_m   = (const float*)d_in[11];
    const float* kv_v   = (const float*)d_in[12];
    const float* kv_pw  = (const float*)d_in[13];
    const float* out_w  = (const float*)d_in[14];
    const float* out_b  = (const float*)d_in[15];
    float* out = (float*)d_out;

    __nv_bfloat16 *wq_h, *wq_l, *wkv_h, *wkv_l, *wo_h, *wo_l;
    __nv_bfloat16 *hq_h, *hq_l, *hkv_h, *hkv_l, *q_hp, *q_lp, *kv_hp, *kv_lp, *ao_h, *ao_l;
    cudaGetSymbolAddress((void**)&wq_h,  g_wq_h);  cudaGetSymbolAddress((void**)&wq_l,  g_wq_l);
    cudaGetSymbolAddress((void**)&wkv_h, g_wkv_h); cudaGetSymbolAddress((void**)&wkv_l, g_wkv_l);
    cudaGetSymbolAddress((void**)&wo_h,  g_wo_h);  cudaGetSymbolAddress((void**)&wo_l,  g_wo_l);
    cudaGetSymbolAddress((void**)&hq_h,  g_hq_h);  cudaGetSymbolAddress((void**)&hq_l,  g_hq_l);
    cudaGetSymbolAddress((void**)&hkv_h, g_hkv_h); cudaGetSymbolAddress((void**)&hkv_l, g_hkv_l);
    cudaGetSymbolAddress((void**)&q_hp,  g_q_h);   cudaGetSymbolAddress((void**)&q_lp,  g_q_l);
    cudaGetSymbolAddress((void**)&kv_hp, g_kv_h);  cudaGetSymbolAddress((void**)&kv_lp, g_kv_l);
    cudaGetSymbolAddress((void**)&ao_h,  g_ao_h);  cudaGetSymbolAddress((void**)&ao_l,  g_ao_l);

    size_t szHQ  = (size_t)NB * NC * NP1;
    size_t szHKV = (size_t)NB * NC * NP2;
    size_t szQ   = (size_t)NB * NINNER * NP1;
    size_t szKV  = (size_t)NB * 2 * NINNER * NP2;
    size_t szAO  = (size_t)NB * NINNER * NP1;
    size_t szOUT = (size_t)NB * NC * NP1;

    static cudaStream_t s1 = nullptr, s2 = nullptr;
    static cudaEvent_t e_fork, e_cvt, e_dw0, e_dw1, e_q0, e_q1, e_kv1, e_at0, e_at1, e_o0, e_o1;
    if (!s1) {
        cudaStreamCreateWithFlags(&s1, cudaStreamNonBlocking);
        cudaStreamCreateWithFlags(&s2, cudaStreamNonBlocking);
        cudaEventCreateWithFlags(&e_fork, cudaEventDisableTiming);
        cudaEventCreateWithFlags(&e_cvt,  cudaEventDisableTiming);
        cudaEventCreateWithFlags(&e_dw0,  cudaEventDisableTiming);
        cudaEventCreateWithFlags(&e_dw1,  cudaEventDisableTiming);
        cudaEventCreateWithFlags(&e_q0,   cudaEventDisableTiming);
        cudaEventCreateWithFlags(&e_q1,   cudaEventDisableTiming);
        cudaEventCreateWithFlags(&e_kv1,  cudaEventDisableTiming);
        cudaEventCreateWithFlags(&e_at0,  cudaEventDisableTiming);
        cudaEventCreateWithFlags(&e_at1,  cudaEventDisableTiming);
        cudaEventCreateWithFlags(&e_o0,   cudaEventDisableTiming);
        cudaEventCreateWithFlags(&e_o1,   cudaEventDisableTiming);
        cudaFuncSetAttribute(mm_attn4, cudaFuncAttributeMaxDynamicSharedMemorySize, ATT_SM4);
        cudaFuncSetAttribute(mm_gemm2, cudaFuncAttributeMaxDynamicSharedMemorySize, GSM2);
    }

    cudaEventRecord(e_fork, 0);
    cudaStreamWaitEvent(s1, e_fork, 0);
    cudaStreamWaitEvent(s2, e_fork, 0);

    // s1: weight conversions
    cvt_hl_kernel<<<(NINNER * NC / 2 + 255) / 256, 256, 0, s1>>>(q_pw,  wq_h,  wq_l,  NINNER * NC / 2);
    cvt_hl_kernel<<<(2 * NINNER * NC / 2 + 255) / 256, 256, 0, s1>>>(kv_pw, wkv_h, wkv_l, 2 * NINNER * NC / 2);
    cvt_hl_kernel<<<(NC * NINNER / 2 + 255) / 256, 256, 0, s1>>>(out_w, wo_h,  wo_l,  NC * NINNER / 2);
    cudaEventRecord(e_cvt, s1);

    // stream0: dwbn per input
    dwbn_fused<<<NB * NC, 256>>>(x, y, q_dw_w, q_g, q_b, q_m, q_v,
                                 kv_dw_w, kv_g, kv_b, kv_m, kv_v, 0);
    cudaEventRecord(e_dw0, 0);
    dwbn_fused<<<NB * NC, 256>>>(x, y, q_dw_w, q_g, q_b, q_m, q_v,
                                 kv_dw_w, kv_g, kv_b, kv_m, kv_v, 1);
    cudaEventRecord(e_dw1, 0);

    // s1: kv-proj inp0 then inp1
    cudaStreamWaitEvent(s1, e_dw0, 0);
    mm_gemm2<<<dim3(NP2 / 128, (2 * NINNER) / 128, NB), 256, GSM2, s1>>>(
        wkv_h, wkv_l, hkv_h, hkv_l, kv_hp, kv_lp, nullptr, nullptr,
        2 * NINNER, NC, NP2);
    cudaStreamWaitEvent(s1, e_dw1, 0);
    mm_gemm2<<<dim3(NP2 / 128, (2 * NINNER) / 128, NB), 256, GSM2, s1>>>(
        wkv_h, wkv_l, hkv_h + szHKV, hkv_l + szHKV, kv_hp + szKV, kv_lp + szKV,
        nullptr, nullptr, 2 * NINNER, NC, NP2);
    cudaEventRecord(e_kv1, s1);

    // stream0: q-proj inp0 then inp1
    cudaStreamWaitEvent(0, e_cvt, 0);
    mm_gemm2<<<dim3(NP1 / 128, NINNER / 128, NB), 256, GSM2>>>(
        wq_h, wq_l, hq_h, hq_l, q_hp, q_lp, nullptr, nullptr,
        NINNER, NC, NP1);
    cudaEventRecord(e_q0, 0);
    mm_gemm2<<<dim3(NP1 / 128, NINNER / 128, NB), 256, GSM2>>>(
        wq_h, wq_l, hq_h + szHQ, hq_l + szHQ, q_hp + szQ, q_lp + szQ,
        nullptr, nullptr, NINNER, NC, NP1);
    cudaEventRecord(e_q1, 0);

    // s2: attn dir0 (needs q0 + kv1), 128 CTAs
    cudaStreamWaitEvent(s2, e_q0, 0);
    cudaStreamWaitEvent(s2, e_kv1, 0);
    mm_attn4<<<dim3(NB * 8, 2), 512, ATT_SM4, s2>>>(0);
    cudaEventRecord(e_at0, s2);

    // s1: attn dir1 (needs q1; kv0 ordered on s1), 128 CTAs
    cudaStreamWaitEvent(s1, e_q1, 0);
    mm_attn4<<<dim3(NB * 8, 2), 512, ATT_SM4, s1>>>(1);
    cudaEventRecord(e_at1, s1);

    // out-proj split by direction: dir0 half on s2, dir1 half on s1
    mm_gemm2<<<dim3(NP1 / 128, NC / 128, NB), 256, GSM2, s2>>>(
        wo_h, wo_l, ao_h, ao_l, nullptr, nullptr, out, out_b,
        NC, NINNER, NP1);
    cudaEventRecord(e_o0, s2);
    mm_gemm2<<<dim3(NP1 / 128, NC / 128, NB), 256, GSM2, s1>>>(
        wo_h, wo_l, ao_h + szAO, ao_l + szAO, nullptr, nullptr, out + szOUT, out_b,
        NC, NINNER, NP1);
    cudaEventRecord(e_o1, s1);

    // join back to stream 0
    cudaStreamWaitEvent(0, e_o0, 0);
    cudaStreamWaitEvent(0, e_o1, 0);
}

// round 16
// speedup vs baseline: 1.1018x; 1.0368x over previous
#include <cuda_runtime.h>
#include <cuda_bf16.h>
#include <stdint.h>
#include <math.h>

#define NB 8
#define NC 256
#define NP1 1024
#define NP2 256
#define NINNER 512
#define BN_EPS 1e-5f

// ---------------- bf16 hi/lo scratch ----------------
__device__ __nv_bfloat16 g_hq_h [2][NB][NC][NP1],      g_hq_l [2][NB][NC][NP1];
__device__ __nv_bfloat16 g_hkv_h[2][NB][NC][NP2],      g_hkv_l[2][NB][NC][NP2];
__device__ __nv_bfloat16 g_q_h  [2][NB][NINNER][NP1],  g_q_l  [2][NB][NINNER][NP1];
__device__ __nv_bfloat16 g_kv_h [2][NB][2*NINNER][NP2],g_kv_l [2][NB][2*NINNER][NP2];
__device__ __nv_bfloat16 g_ao_h [2][NB][NINNER][NP1],  g_ao_l [2][NB][NINNER][NP1];
__device__ __nv_bfloat16 g_wq_h [NINNER*NC],   g_wq_l [NINNER*NC];
__device__ __nv_bfloat16 g_wkv_h[2*NINNER*NC], g_wkv_l[2*NINNER*NC];
__device__ __nv_bfloat16 g_wo_h [NC*NINNER],   g_wo_l [NC*NINNER];

// ---------------- helpers ----------------
__device__ __forceinline__ uint32_t smem_u32(const void* p){
    uint32_t a;
    asm("{ .reg .u64 t; cvta.to.shared.u64 t, %1; cvt.u32.u64 %0, t; }" : "=r"(a) : "l"(p));
    return a;
}
__device__ __forceinline__ void ldmx4(uint32_t* r, uint32_t a){
    asm volatile("ldmatrix.sync.aligned.m8n8.x4.shared.b16 {%0,%1,%2,%3}, [%4];"
        : "=r"(r[0]),"=r"(r[1]),"=r"(r[2]),"=r"(r[3]) : "r"(a) : "memory");
}
__device__ __forceinline__ void ldmx4t(uint32_t* r, uint32_t a){
    asm volatile("ldmatrix.sync.aligned.m8n8.x4.trans.shared.b16 {%0,%1,%2,%3}, [%4];"
        : "=r"(r[0]),"=r"(r[1]),"=r"(r[2]),"=r"(r[3]) : "r"(a) : "memory");
}
__device__ __forceinline__ void mma16816(float* c, const uint32_t* a, const uint32_t* b){
    asm volatile("mma.sync.aligned.m16n8k16.row.col.f32.bf16.bf16.f32 "
        "{%0,%1,%2,%3}, {%4,%5,%6,%7}, {%8,%9}, {%0,%1,%2,%3};"
        : "+f"(c[0]),"+f"(c[1]),"+f"(c[2]),"+f"(c[3])
        : "r"(a[0]),"r"(a[1]),"r"(a[2]),"r"(a[3]),"r"(b[0]),"r"(b[1]));
}
__device__ __forceinline__ void cpa16(uint32_t s, const void* g){
    asm volatile("cp.async.cg.shared.global [%0], [%1], 16;" :: "r"(s), "l"(g));
}
#define CP_COMMIT() asm volatile("cp.async.commit_group;" ::: "memory")
#define CP_WAIT0()  asm volatile("cp.async.wait_group 0;" ::: "memory")
#define CP_WAIT1()  asm volatile("cp.async.wait_group 1;" ::: "memory")

__device__ __forceinline__ uint32_t pack_bf2(float v0, float v1){
    uint32_t p;
    asm("cvt.rn.bf16x2.f32 %0, %1, %2;" : "=r"(p) : "f"(v1), "f"(v0));
    return p;
}
__device__ __forceinline__ void put_hl2(__nv_bfloat16* bh, __nv_bfloat16* bl, int idx, float v0, float v1){
    uint32_t hp = pack_bf2(v0, v1);
    float h0 = __uint_as_float(hp << 16);
    float h1 = __uint_as_float(hp & 0xFFFF0000u);
    uint32_t lp = pack_bf2(v0 - h0, v1 - h1);
    *(uint32_t*)(bh + idx) = hp;
    *(uint32_t*)(bl + idx) = lp;
}
__device__ __forceinline__ void put_hl4(__nv_bfloat16* bh, __nv_bfloat16* bl, int idx,
                                        float v0, float v1, float v2, float v3){
    uint32_t hp0 = pack_bf2(v0, v1), hp1 = pack_bf2(v2, v3);
    float h0 = __uint_as_float(hp0 << 16), h1 = __uint_as_float(hp0 & 0xFFFF0000u);
    float h2 = __uint_as_float(hp1 << 16), h3 = __uint_as_float(hp1 & 0xFFFF0000u);
    uint32_t lp0 = pack_bf2(v0 - h0, v1 - h1), lp1 = pack_bf2(v2 - h2, v3 - h3);
    *(uint2*)(bh + idx) = make_uint2(hp0, hp1);
    *(uint2*)(bl + idx) = make_uint2(lp0, lp1);
}
__device__ __forceinline__ void put_hl(__nv_bfloat16* bh, __nv_bfloat16* bl, int idx, float v){
    __nv_bfloat16 h = __float2bfloat16(v);
    bh[idx] = h;
    float hf = __uint_as_float(((uint32_t)__bfloat16_as_ushort(h)) << 16);
    bl[idx] = __float2bfloat16(v - hf);
}
// build hi+lo A-fragments for P from accumulator chunks (rows own-warp)
__device__ __forceinline__ void frag_hl(const float* e0, const float* e1,
                                        uint32_t* ah, uint32_t* al){
    ah[0] = pack_bf2(e0[0], e0[1]);
    ah[1] = pack_bf2(e0[2], e0[3]);
    ah[2] = pack_bf2(e1[0], e1[1]);
    ah[3] = pack_bf2(e1[2], e1[3]);
    al[0] = pack_bf2(e0[0] - __uint_as_float(ah[0] << 16), e0[1] - __uint_as_float(ah[0] & 0xFFFF0000u));
    al[1] = pack_bf2(e0[2] - __uint_as_float(ah[1] << 16), e0[3] - __uint_as_float(ah[1] & 0xFFFF0000u));
    al[2] = pack_bf2(e1[0] - __uint_as_float(ah[2] << 16), e1[1] - __uint_as_float(ah[2] & 0xFFFF0000u));
    al[3] = pack_bf2(e1[2] - __uint_as_float(ah[3] << 16), e1[3] - __uint_as_float(ah[3] & 0xFFFF0000u));
}

// ---------------- weight fp32 -> hi/lo (with exact scale) ----------------
__global__ void cvt_hl_kernel(const float* __restrict__ src, __nv_bfloat16* __restrict__ h,
                              __nv_bfloat16* __restrict__ l, int n2, float scale){
    int i = blockIdx.x * 256 + threadIdx.x;
    if (i < n2) {
        float2 v = *(const float2*)(src + i * 2);
        put_hl2(h, l, i * 2, v.x * scale, v.y * scale);
    }
}

// ---------------- fused depthwise conv (s1 + s2) + BN, per-input ----------------
__global__ __launch_bounds__(256)
void dwbn_fused(const float* __restrict__ x0, const float* __restrict__ x1,
                const float* __restrict__ qw, const float* __restrict__ qg,
                const float* __restrict__ qb, const float* __restrict__ qm,
                const float* __restrict__ qv,
                const float* __restrict__ kw, const float* __restrict__ kg,
                const float* __restrict__ kb, const float* __restrict__ km,
                const float* __restrict__ kvv, int inp)
{
    int bc = blockIdx.x, c = bc & 255, b = bc >> 8;
    const float* in = (inp ? x1 : x0) + (size_t)bc * 1024;
    __shared__ float t[34][36];
    int tid = threadIdx.x;

    if (tid < 34) { t[0][tid] = 0.f; t[33][tid] = 0.f; }
    else if (tid < 66) { int r = tid - 33; t[r][0] = 0.f; t[r][33] = 0.f; }

    {
        int r = tid >> 3, q = (tid & 7) * 4;
        float4 v = *(const float4*)(in + r * 32 + q);
        t[r + 1][q + 1] = v.x; t[r + 1][q + 2] = v.y;
        t[r + 1][q + 3] = v.z; t[r + 1][q + 4] = v.w;
    }

    float qwr[9], kwr[9];
#pragma unroll
    for (int i = 0; i < 9; i++) { qwr[i] = qw[c * 9 + i]; kwr[i] = kw[c * 9 + i]; }
    float qs  = qg[c] * rsqrtf(qv[c] + BN_EPS);
    float qsh = qb[c] - qm[c] * qs;
    float ks  = kg[c] * rsqrtf(kvv[c] + BN_EPS);
    float ksh = kb[c] - km[c] * ks;
    __syncthreads();

    {
        int oy = tid >> 3, ox = (tid & 7) * 4;
        float o0 = 0.f, o1 = 0.f, o2 = 0.f, o3 = 0.f;
#pragma unroll
        for (int dy = 0; dy < 3; dy++) {
            float a0 = t[oy + dy][ox + 0], a1 = t[oy + dy][ox + 1], a2 = t[oy + dy][ox + 2];
            float a3 = t[oy + dy][ox + 3], a4 = t[oy + dy][ox + 4], a5 = t[oy + dy][ox + 5];
            float w0 = qwr[dy * 3], w1 = qwr[dy * 3 + 1], w2 = qwr[dy * 3 + 2];
            o0 += a0 * w0 + a1 * w1 + a2 * w2;
            o1 += a1 * w0 + a2 * w1 + a3 * w2;
            o2 += a2 * w0 + a3 * w1 + a4 * w2;
            o3 += a3 * w0 + a4 * w1 + a5 * w2;
        }
        o0 = o0 * qs + qsh; o1 = o1 * qs + qsh;
        o2 = o2 * qs + qsh; o3 = o3 * qs + qsh;
        put_hl4(&g_hq_h[inp][b][c][0], &g_hq_l[inp][b][c][0], oy * 32 + ox, o0, o1, o2, o3);
    }

    {
        int oy = tid >> 4, ox = tid & 15;
        float a = 0.f;
#pragma unroll
        for (int dy = 0; dy < 3; dy++)
#pragma unroll
            for (int dx = 0; dx < 3; dx++)
                a += t[oy * 2 + dy][ox * 2 + dx] * kwr[dy * 3 + dx];
        a = a * ks + ksh;
        put_hl(&g_hkv_h[inp][b][c][0], &g_hkv_l[inp][b][c][0], oy * 16 + ox, a);
    }
}

// ---------------- tensor-core GEMM (2-stage, 2 CTAs/SM) ----------------
#define ALD2 40
#define BLD2 136
#define A_H0 0
#define A_H1 10240
#define A_L0 20480
#define A_L1 30720
#define B_H0 40960
#define B_H1 49664
#define B_L0 58368
#define B_L1 67072
#define GSM2 75776
#define ELD 136
#define ELDF 136

__global__ __launch_bounds__(256, 2)
void mm_gemm2(const __nv_bfloat16* __restrict__ Ah, const __nv_bfloat16* __restrict__ Al,
              const __nv_bfloat16* __restrict__ Bh, const __nv_bfloat16* __restrict__ Bl,
              __nv_bfloat16* __restrict__ Ch, __nv_bfloat16* __restrict__ Cl,
              float* __restrict__ Cf, const float* __restrict__ bias,
              int Mtot, int K, int P)
{
    extern __shared__ char sm[];
    uint32_t sb = smem_u32(sm);
    int tid = threadIdx.x, lane = tid & 31, wid = tid >> 5;
    int wr = wid >> 1, wc = wid & 1;
    int m0 = blockIdx.y * 128, n0 = blockIdx.x * 128;
    size_t zoff = (size_t)blockIdx.z * K * P;
    const __nv_bfloat16* Bhz = Bh + zoff;
    const __nv_bfloat16* Blz = Bl + zoff;

    float acc[2][8][4];
#pragma unroll
    for (int i = 0; i < 2; i++)
#pragma unroll
        for (int j = 0; j < 8; j++)
#pragma unroll
            for (int k = 0; k < 4; k++) acc[i][j][k] = 0.f;

    int niter = K >> 5;

#define LOAD_STAGE(st, k0) do { \
    uint32_t aH = sb + ((st) ? A_H1 : A_H0); \
    uint32_t aL = sb + ((st) ? A_L1 : A_L0); \
    uint32_t bH = sb + ((st) ? B_H1 : B_H0); \
    uint32_t bL = sb + ((st) ? B_L1 : B_L0); \
    _Pragma("unroll") \
    for (int u = 0; u < 2; u++) { \
        int idx = tid + u * 256; \
        int row = idx >> 2, ch = (idx & 3) * 8; \
        size_t go = (size_t)(m0 + row) * K + (k0) + ch; \
        uint32_t so = (uint32_t)(row * ALD2 + ch) * 2; \
        cpa16(aH + so, Ah + go); \
        cpa16(aL + so, Al + go); \
    } \
    _Pragma("unroll") \
    for (int u = 0; u < 2; u++) { \
        int idx = tid + u * 256; \
        int row = idx >> 4, ch = (idx & 15) * 8; \
        size_t go = (size_t)((k0) + row) * P + n0 + ch; \
        uint32_t so = (uint32_t)(row * BLD2 + ch) * 2; \
        cpa16(bH + so, Bhz + go); \
        cpa16(bL + so, Blz + go); \
    } \
} while (0)

    LOAD_STAGE(0, 0);
    CP_COMMIT();

    for (int it = 0; it < niter; it++) {
        if (it + 1 < niter) { LOAD_STAGE((it + 1) & 1, (it + 1) << 5); CP_COMMIT(); CP_WAIT1(); }
        else CP_WAIT0();
        __syncthreads();

        uint32_t aHb = sb + ((it & 1) ? A_H1 : A_H0);
        uint32_t bHb = sb + ((it & 1) ? B_H1 : B_H0);
#pragma unroll
        for (int kk = 0; kk < 2; kk++) {
            uint32_t ah[2][4], al[2][4];
#pragma unroll
            for (int mi = 0; mi < 2; mi++) {
                uint32_t aaddr = aHb + (uint32_t)((wr*32 + mi*16 + (lane & 15)) * ALD2
                                                  + kk*16 + (lane >> 4) * 8) * 2;
                ldmx4(ah[mi], aaddr);
                ldmx4(al[mi], aaddr + 20480u);
            }
#pragma unroll
            for (int ni2 = 0; ni2 < 4; ni2++) {
                uint32_t bh[4], bl[4];
                uint32_t baddr = bHb + (uint32_t)((kk*16 + (lane & 15)) * BLD2
                                                  + wc*64 + ni2*16 + ((lane & 16) >> 1)) * 2;
                ldmx4t(bh, baddr);
                ldmx4t(bl, baddr + 17408u);
#pragma unroll
                for (int mi = 0; mi < 2; mi++) {
                    mma16816(acc[mi][ni2*2],   ah[mi], &bh[0]);
                    mma16816(acc[mi][ni2*2],   ah[mi], &bl[0]);
                    mma16816(acc[mi][ni2*2],   al[mi], &bh[0]);
                    mma16816(acc[mi][ni2*2+1], ah[mi], &bh[2]);
                    mma16816(acc[mi][ni2*2+1], ah[mi], &bl[2]);
                    mma16816(acc[mi][ni2*2+1], al[mi], &bh[2]);
                }
            }
        }
        __syncthreads();
    }

    if (Cf) {
        float* Ef = (float*)sm;
        float* Cp = Cf + (size_t)blockIdx.z * Mtot * P;
#pragma unroll
        for (int mi = 0; mi < 2; mi++) {
            int row = wr*32 + mi*16 + (lane >> 2);
            float b0 = bias ? bias[m0 + row] : 0.f;
            float b1 = bias ? bias[m0 + row + 8] : 0.f;
#pragma unroll
            for (int ni = 0; ni < 8; ni++) {
                int col = wc*64 + ni*8 + (lane & 3) * 2;
                *(float2*)&Ef[row * ELDF + col] =
                    make_float2(acc[mi][ni][0] + b0, acc[mi][ni][1] + b0);
                *(float2*)&Ef[(row + 8) * ELDF + col] =
                    make_float2(acc[mi][ni][2] + b1, acc[mi][ni][3] + b1);
            }
        }
        __syncthreads();
#pragma unroll
        for (int u = 0; u < 16; u++) {
            int linear = tid + u * 256;
            int row = linear >> 5, c4 = (linear & 31) * 4;
            *(float4*)&Cp[(size_t)(m0 + row) * P + n0 + c4] =
                *(const float4*)&Ef[row * ELDF + c4];
        }
    } else {
        __nv_bfloat16* Eh = (__nv_bfloat16*)sm;
        __nv_bfloat16* El = (__nv_bfloat16*)(sm + 128 * ELD * 2);
#pragma unroll
        for (int mi = 0; mi < 2; mi++) {
            int row = wr*32 + mi*16 + (lane >> 2);
#pragma unroll
            for (int ni = 0; ni < 8; ni++) {
                int col = wc*64 + ni*8 + (lane & 3) * 2;
                put_hl2(Eh, El, row * ELD + col, acc[mi][ni][0], acc[mi][ni][1]);
                put_hl2(Eh, El, (row + 8) * ELD + col, acc[mi][ni][2], acc[mi][ni][3]);
            }
        }
        __syncthreads();
        __nv_bfloat16* Chz = Ch + (size_t)blockIdx.z * Mtot * P;
        __nv_bfloat16* Clz = Cl + (size_t)blockIdx.z * Mtot * P;
#pragma unroll
        for (int u = 0; u < 8; u++) {
            int linear = tid + u * 256;
            int row = linear >> 4, c8 = (linear & 15) * 8;
            size_t go = (size_t)(m0 + row) * P + n0 + c8;
            *(uint4*)&Chz[go] = *(const uint4*)&Eh[row * ELD + c8];
            *(uint4*)&Clz[go] = *(const uint4*)&El[row * ELD + c8];
        }
    }
}

// ---------------- fused attention v8: register-resident P (FA2 style) ----------------
// 16 warps: wg = wid>>1 (8 row-groups, i-tile 128), wj = wid&1 (j-half of 128).
// smem: Q [64 d][136 i] hi/lo | K [64 d][264 j] hi/lo | V same | O [128][68] f32 | red
#define QLD5 136
#define KLD5 264
#define OLD5 68
#define BQH 0
#define BQL 17408
#define BKH 34816
#define BKL 68608
#define BVH 102400
#define BVL 136192
#define BO  169984
#define BRM 204800
#define BRS 205824
#define ATT_SM5 206848

__global__ __launch_bounds__(512)
void mm_attn5(int dir)
{
    extern __shared__ char sm[];
    uint32_t sb = smem_u32(sm);
    float* red_m = (float*)(sm + BRM);
    float* red_s = (float*)(sm + BRS);
    float* O = (float*)(sm + BO);

    int tid = threadIdx.x, lane = tid & 31, wid = tid >> 5;
    int bh = blockIdx.x;
    int b = bh >> 3, h = bh & 7;
    int it0 = blockIdx.y * 4;           // 4 i-tiles of 128 per CTA
    int qin = dir, kin = dir ^ 1;
    int wg = wid >> 1, wj = wid & 1;

    const __nv_bfloat16* qh = &g_q_h[qin][b][0][0];
    const __nv_bfloat16* ql = &g_q_l[qin][b][0][0];
    const __nv_bfloat16* kh = &g_kv_h[kin][b][0][0];
    const __nv_bfloat16* kl = &g_kv_l[kin][b][0][0];

    // Q loader: 512 threads, two planes; per thread 32 contiguous i (4x cpa16)
    int qhalf = tid >> 8, qt = tid & 255;
    int qd = qt >> 2, qch = (qt & 3) * 32;
    const __nv_bfloat16* qsrc = (qhalf ? ql : qh) + (size_t)(h * 64 + qd) * NP1 + it0 * 128 + qch;
    uint32_t qdst = sb + (qhalf ? BQL : BQH) + (uint32_t)(qd * QLD5 + qch) * 2;

    // K, V resident
#pragma unroll
    for (int u = 0; u < 4; u++) {
        int idx = tid + u * 512;
        int d = idx >> 5, ch = (idx & 31) * 8;
        size_t gk = (size_t)(h * 64 + d) * NP2 + ch;
        size_t gv = (size_t)(NINNER + h * 64 + d) * NP2 + ch;
        uint32_t so = (uint32_t)(d * KLD5 + ch) * 2;
        cpa16(sb + BKH + so, kh + gk);
        cpa16(sb + BKL + so, kl + gk);
        cpa16(sb + BVH + so, kh + gv);
        cpa16(sb + BVL + so, kl + gv);
    }
#pragma unroll
    for (int f = 0; f < 4; f++) cpa16(qdst + f * 16, qsrc + f * 8);
    CP_COMMIT();

    int g = lane >> 2;
    int rA = wg * 16 + g;          // local row 0..127
    int rB = rA + 8;

    for (int lt = 0; lt < 4; lt++) {
        CP_WAIT0();
        __syncthreads();           // Q ready; O region free
        int i0 = (it0 + lt) * 128;

        // phase 1: S rows [wg*16,+16) x cols [wj*128,+128)
        float acc[16][4];
#pragma unroll
        for (int i = 0; i < 16; i++)
#pragma unroll
            for (int k = 0; k < 4; k++) acc[i][k] = 0.f;

#pragma unroll
        for (int kk = 0; kk < 4; kk++) {
            uint32_t ah[4], al[4];
            uint32_t krow = (uint32_t)(kk*16 + (lane & 7) + ((lane >> 1) & 8));
            uint32_t acol = (uint32_t)(wg*16 + (lane & 8));
            uint32_t aaddr = sb + BQH + (krow * QLD5 + acol) * 2;
            ldmx4t(ah, aaddr);
            ldmx4t(al, aaddr + (BQL - BQH));
#pragma unroll
            for (int ni2 = 0; ni2 < 8; ni2++) {
                uint32_t bhf[4], blf[4];
                uint32_t baddr = sb + BKH + (uint32_t)((kk*16 + (lane & 15)) * KLD5
                                                       + wj*128 + ni2*16 + ((lane & 16) >> 1)) * 2;
                ldmx4t(bhf, baddr);
                ldmx4t(blf, baddr + (BKL - BKH));
                mma16816(acc[ni2*2],   ah, &bhf[0]);
                mma16816(acc[ni2*2],   ah, &blf[0]);
                mma16816(acc[ni2*2],   al, &bhf[0]);
                mma16816(acc[ni2*2+1], ah, &bhf[2]);
                mma16816(acc[ni2*2+1], ah, &blf[2]);
                mma16816(acc[ni2*2+1], al, &bhf[2]);
            }
        }

        // row max within warp's 128 cols (scale already folded into wq)
        float mA = -1e30f, mB = -1e30f;
#pragma unroll
        for (int ni = 0; ni < 16; ni++) {
            mA = fmaxf(mA, fmaxf(acc[ni][0], acc[ni][1]));
            mB = fmaxf(mB, fmaxf(acc[ni][2], acc[ni][3]));
        }
        mA = fmaxf(mA, __shfl_xor_sync(0xffffffffu, mA, 1));
        mA = fmaxf(mA, __shfl_xor_sync(0xffffffffu, mA, 2));
        mB = fmaxf(mB, __shfl_xor_sync(0xffffffffu, mB, 1));
        mB = fmaxf(mB, __shfl_xor_sync(0xffffffffu, mB, 2));
        if ((lane & 3) == 0) { red_m[rA * 2 + wj] = mA; red_m[rB * 2 + wj] = mB; }
        __syncthreads();           // also: all Q reads done -> prefetch next Q
        if (lt + 1 < 4) {
            const __nv_bfloat16* nq = qsrc + (lt + 1) * 128;
#pragma unroll
            for (int f = 0; f < 4; f++) cpa16(qdst + f * 16, nq + f * 8);
            CP_COMMIT();
        }
        mA = fmaxf(red_m[rA * 2], red_m[rA * 2 + 1]);
        mB = fmaxf(red_m[rB * 2], red_m[rB * 2 + 1]);

        float sA = 0.f, sB = 0.f;
#pragma unroll
        for (int ni = 0; ni < 16; ni++) {
            acc[ni][0] = __expf(acc[ni][0] - mA);
            acc[ni][1] = __expf(acc[ni][1] - mA);
            acc[ni][2] = __expf(acc[ni][2] - mB);
            acc[ni][3] = __expf(acc[ni][3] - mB);
            sA += acc[ni][0] + acc[ni][1];
            sB += acc[ni][2] + acc[ni][3];
        }
        sA += __shfl_xor_sync(0xffffffffu, sA, 1);
        sA += __shfl_xor_sync(0xffffffffu, sA, 2);
        sB += __shfl_xor_sync(0xffffffffu, sB, 1);
        sB += __shfl_xor_sync(0xffffffffu, sB, 2);
        if ((lane & 3) == 0) { red_s[rA * 2 + wj] = sA; red_s[rB * 2 + wj] = sB; }
        __syncthreads();

        // phase 2: O partial over this warp's j-half; P fragments from registers
        float acc2[8][4];
#pragma unroll
        for (int i = 0; i < 8; i++)
#pragma unroll
            for (int k = 0; k < 4; k++) acc2[i][k] = 0.f;

#pragma unroll
        for (int kk = 0; kk < 8; kk++) {
            uint32_t pah[4], pal[4];
            frag_hl(acc[2*kk], acc[2*kk+1], pah, pal);
#pragma unroll
            for (int ni2 = 0; ni2 < 4; ni2++) {
                uint32_t vh[4], vl[4];
                uint32_t baddr = sb + BVH + (uint32_t)((ni2*16 + ((lane >> 4) & 1) * 8 + (lane & 7)) * KLD5
                                                       + wj*128 + kk*16 + ((lane >> 3) & 1) * 8) * 2;
                ldmx4(vh, baddr);
                ldmx4(vl, baddr + (BVL - BVH));
                mma16816(acc2[ni2*2],   pah, &vh[0]);
                mma16816(acc2[ni2*2],   pah, &vl[0]);
                mma16816(acc2[ni2*2],   pal, &vh[0]);
                mma16816(acc2[ni2*2+1], pah, &vh[2]);
                mma16816(acc2[ni2*2+1], pah, &vl[2]);
                mma16816(acc2[ni2*2+1], pal, &vh[2]);
            }
        }

        float invA = 1.f / (red_s[rA * 2] + red_s[rA * 2 + 1]);
        float invB = 1.f / (red_s[rB * 2] + red_s[rB * 2 + 1]);

        // combine partials: wj==0 writes scaled, sync, wj==1 adds scaled
        if (wj == 0) {
#pragma unroll
            for (int ni = 0; ni < 8; ni++) {
                int c = ni*8 + (lane & 3) * 2;
                O[rA * OLD5 + c]     = acc2[ni][0] * invA;
                O[rA * OLD5 + c + 1] = acc2[ni][1] * invA;
                O[rB * OLD5 + c]     = acc2[ni][2] * invB;
                O[rB * OLD5 + c + 1] = acc2[ni][3] * invB;
            }
        }
        __syncthreads();
        if (wj == 1) {
#pragma unroll
            for (int ni = 0; ni < 8; ni++) {
                int c = ni*8 + (lane & 3) * 2;
                O[rA * OLD5 + c]     += acc2[ni][0] * invA;
                O[rA * OLD5 + c + 1] += acc2[ni][1] * invA;
                O[rB * OLD5 + c]     += acc2[ni][2] * invB;
                O[rB * OLD5 + c + 1] += acc2[ni][3] * invB;
            }
        }
        __syncthreads();

        // store O [128 i][64 d] -> g_ao [d][i] hi/lo, coalesced over i
        {
            int d = tid >> 3, ip = (tid & 7) * 16;
            __nv_bfloat16* aoh = &g_ao_h[qin][b][h * 64 + d][i0 + ip];
            __nv_bfloat16* aol = &g_ao_l[qin][b][h * 64 + d][i0 + ip];
#pragma unroll
            for (int u = 0; u < 16; u += 2) {
                float v0 = O[(ip + u) * OLD5 + d];
                float v1 = O[(ip + u + 1) * OLD5 + d];
                put_hl2(aoh, aol, u, v0, v1);
            }
        }
    }
}

// ---------------- launch ----------------
extern "C" void kernel_launch(void* const* d_in, const int* in_sizes, int n_in,
                              void* d_out, int out_size)
{
    const float* x      = (const float*)d_in[0];
    const float* y      = (const float*)d_in[1];
    const float* q_dw_w = (const float*)d_in[2];
    const float* q_g    = (const float*)d_in[3];
    const float* q_b    = (const float*)d_in[4];
    const float* q_m    = (const float*)d_in[5];
    const float* q_v    = (const float*)d_in[6];
    const float* q_pw   = (const float*)d_in[7];
    const float* kv_dw_w= (const float*)d_in[8];
    const float* kv_g   = (const float*)d_in[9];
    const float* kv_b   = (const float*)d_in[10];
    const float* kv_m   = (const float*)d_in[11];
    const float* kv_v   = (const float*)d_in[12];
    const float* kv_pw  = (const float*)d_in[13];
    const float* out_w  = (const float*)d_in[14];
    const float* out_b  = (const float*)d_in[15];
    float* out = (float*)d_out;

    __nv_bfloat16 *wq_h, *wq_l, *wkv_h, *wkv_l, *wo_h, *wo_l;
    __nv_bfloat16 *hq_h, *hq_l, *hkv_h, *hkv_l, *q_hp, *q_lp, *kv_hp, *kv_lp, *ao_h, *ao_l;
    cudaGetSymbolAddress((void**)&wq_h,  g_wq_h);  cudaGetSymbolAddress((void**)&wq_l,  g_wq_l);
    cudaGetSymbolAddress((void**)&wkv_h, g_wkv_h); cudaGetSymbolAddress((void**)&wkv_l, g_wkv_l);
    cudaGetSymbolAddress((void**)&wo_h,  g_wo_h);  cudaGetSymbolAddress((void**)&wo_l,  g_wo_l);
    cudaGetSymbolAddress((void**)&hq_h,  g_hq_h);  cudaGetSymbolAddress((void**)&hq_l,  g_hq_l);
    cudaGetSymbolAddress((void**)&hkv_h, g_hkv_h); cudaGetSymbolAddress((void**)&hkv_l, g_hkv_l);
    cudaGetSymbolAddress((void**)&q_hp,  g_q_h);   cudaGetSymbolAddress((void**)&q_lp,  g_q_l);
    cudaGetSymbolAddress((void**)&kv_hp, g_kv_h);  cudaGetSymbolAddress((void**)&kv_lp, g_kv_l);
    cudaGetSymbolAddress((void**)&ao_h,  g_ao_h);  cudaGetSymbolAddress((void**)&ao_l,  g_ao_l);

    size_t szHQ  = (size_t)NB * NC * NP1;
    size_t szHKV = (size_t)NB * NC * NP2;
    size_t szQ   = (size_t)NB * NINNER * NP1;
    size_t szKV  = (size_t)NB * 2 * NINNER * NP2;
    size_t szAO  = (size_t)NB * NINNER * NP1;
    size_t szOUT = (size_t)NB * NC * NP1;

    static cudaStream_t s1 = nullptr, s2 = nullptr;
    static cudaEvent_t e_fork, e_cvt, e_dw0, e_dw1, e_q0, e_q1, e_kv1, e_o0, e_o1;
    if (!s1) {
        cudaStreamCreateWithFlags(&s1, cudaStreamNonBlocking);
        cudaStreamCreateWithFlags(&s2, cudaStreamNonBlocking);
        cudaEventCreateWithFlags(&e_fork, cudaEventDisableTiming);
        cudaEventCreateWithFlags(&e_cvt,  cudaEventDisableTiming);
        cudaEventCreateWithFlags(&e_dw0,  cudaEventDisableTiming);
        cudaEventCreateWithFlags(&e_dw1,  cudaEventDisableTiming);
        cudaEventCreateWithFlags(&e_q0,   cudaEventDisableTiming);
        cudaEventCreateWithFlags(&e_q1,   cudaEventDisableTiming);
        cudaEventCreateWithFlags(&e_kv1,  cudaEventDisableTiming);
        cudaEventCreateWithFlags(&e_o0,   cudaEventDisableTiming);
        cudaEventCreateWithFlags(&e_o1,   cudaEventDisableTiming);
        cudaFuncSetAttribute(mm_attn5, cudaFuncAttributeMaxDynamicSharedMemorySize, ATT_SM5);
        cudaFuncSetAttribute(mm_gemm2, cudaFuncAttributeMaxDynamicSharedMemorySize, GSM2);
    }

    cudaEventRecord(e_fork, 0);
    cudaStreamWaitEvent(s1, e_fork, 0);
    cudaStreamWaitEvent(s2, e_fork, 0);

    // s1: weight conversions (0.125 attention scale folded into wq — exact)
    cvt_hl_kernel<<<(NINNER * NC / 2 + 255) / 256, 256, 0, s1>>>(q_pw,  wq_h,  wq_l,  NINNER * NC / 2, 0.125f);
    cvt_hl_kernel<<<(2 * NINNER * NC / 2 + 255) / 256, 256, 0, s1>>>(kv_pw, wkv_h, wkv_l, 2 * NINNER * NC / 2, 1.0f);
    cvt_hl_kernel<<<(NC * NINNER / 2 + 255) / 256, 256, 0, s1>>>(out_w, wo_h,  wo_l,  NC * NINNER / 2, 1.0f);
    cudaEventRecord(e_cvt, s1);

    // stream0: dwbn per input
    dwbn_fused<<<NB * NC, 256>>>(x, y, q_dw_w, q_g, q_b, q_m, q_v,
                                 kv_dw_w, kv_g, kv_b, kv_m, kv_v, 0);
    cudaEventRecord(e_dw0, 0);
    dwbn_fused<<<NB * NC, 256>>>(x, y, q_dw_w, q_g, q_b, q_m, q_v,
                                 kv_dw_w, kv_g, kv_b, kv_m, kv_v, 1);
    cudaEventRecord(e_dw1, 0);

    // s1: kv-proj inp0 then inp1
    cudaStreamWaitEvent(s1, e_dw0, 0);
    mm_gemm2<<<dim3(NP2 / 128, (2 * NINNER) / 128, NB), 256, GSM2, s1>>>(
        wkv_h, wkv_l, hkv_h, hkv_l, kv_hp, kv_lp, nullptr, nullptr,
        2 * NINNER, NC, NP2);
    cudaStreamWaitEvent(s1, e_dw1, 0);
    mm_gemm2<<<dim3(NP2 / 128, (2 * NINNER) / 128, NB), 256, GSM2, s1>>>(
        wkv_h, wkv_l, hkv_h + szHKV, hkv_l + szHKV, kv_hp + szKV, kv_lp + szKV,
        nullptr, nullptr, 2 * NINNER, NC, NP2);
    cudaEventRecord(e_kv1, s1);

    // stream0: q-proj inp0 then inp1
    cudaStreamWaitEvent(0, e_cvt, 0);
    mm_gemm2<<<dim3(NP1 / 128, NINNER / 128, NB), 256, GSM2>>>(
        wq_h, wq_l, hq_h, hq_l, q_hp, q_lp, nullptr, nullptr,
        NINNER, NC, NP1);
    cudaEventRecord(e_q0, 0);
    mm_gemm2<<<dim3(NP1 / 128, NINNER / 128, NB), 256, GSM2>>>(
        wq_h, wq_l, hq_h + szHQ, hq_l + szHQ, q_hp + szQ, q_lp + szQ,
        nullptr, nullptr, NINNER, NC, NP1);
    cudaEventRecord(e_q1, 0);

    // s2: attn dir0 (needs q0 + kv1), 128 CTAs
    cudaStreamWaitEvent(s2, e_q0, 0);
    cudaStreamWaitEvent(s2, e_kv1, 0);
    mm_attn5<<<dim3(NB * 8, 2), 512, ATT_SM5, s2>>>(0);

    // s1: attn dir1 (needs q1; kv0 ordered on s1), 128 CTAs
    cudaStreamWaitEvent(s1, e_q1, 0);
    mm_attn5<<<dim3(NB * 8, 2), 512, ATT_SM5, s1>>>(1);

    // out-proj split by direction
    mm_gemm2<<<dim3(NP1 / 128, NC / 128, NB), 256, GSM2, s2>>>(
        wo_h, wo_l, ao_h, ao_l, nullptr, nullptr, out, out_b,
        NC, NINNER, NP1);
    cudaEventRecord(e_o0, s2);
    mm_gemm2<<<dim3(NP1 / 128, NC / 128, NB), 256, GSM2, s1>>>(
        wo_h, wo_l, ao_h + szAO, ao_l + szAO, nullptr, nullptr, out + szOUT, out_b,
        NC, NINNER, NP1);
    cudaEventRecord(e_o1, s1);

    cudaStreamWaitEvent(0, e_o0, 0);
    cudaStreamWaitEvent(0, e_o1, 0);
}